// round 1
// baseline (speedup 1.0000x reference)
#include <cuda_runtime.h>
#include <cuda_bf16.h>
#include <math.h>

// Problem constants
#define BB 2
#define LL 512
#define LM 512
#define DM 256
#define DI 1024
#define DS 128
#define DTR 16
#define NH 8
#define DK 32
#define DFF 1024
#define ROWS (BB*LL)          // 1024
#define XZW (2*DI)            // 2048
#define DBLW (DTR + 2*DS)     // 272

// ---------------- scratch (device globals, no allocation) ----------------
__device__ float g_ln  [ROWS*DM];
__device__ float g_xz  [ROWS*XZW];
__device__ float g_u   [ROWS*DI];
__device__ float g_dbl [ROWS*DBLW];
__device__ float g_dt  [ROWS*DI];
__device__ float g_yact[ROWS*DI];
__device__ float g_h   [ROWS*DM];
__device__ float g_h2  [ROWS*DM];
__device__ float g_q   [ROWS*DM];
__device__ float g_k   [ROWS*DM];
__device__ float g_v   [ROWS*DM];
__device__ float g_att [ROWS*DM];
__device__ float g_ffh [ROWS*DFF];

// ---------------- LayerNorm: one block (256 thr) per row ----------------
__global__ void ln_kernel(const float* __restrict__ x,
                          const float* __restrict__ a,
                          const float* __restrict__ b,
                          float* __restrict__ out)
{
    int row = blockIdx.x;
    int t = threadIdx.x;
    float v = x[row*DM + t];
    __shared__ float red[DM];
    red[t] = v; __syncthreads();
    #pragma unroll
    for (int s = 128; s > 0; s >>= 1) { if (t < s) red[t] += red[t+s]; __syncthreads(); }
    float mean = red[0] * (1.0f/DM);
    __syncthreads();
    float dx = v - mean;
    red[t] = dx*dx; __syncthreads();
    #pragma unroll
    for (int s = 128; s > 0; s >>= 1) { if (t < s) red[t] += red[t+s]; __syncthreads(); }
    float var = red[0] * (1.0f/(DM-1));
    float stdv = sqrtf(var);
    out[row*DM + t] = a[t]*dx/(stdv + 1e-6f) + b[t];
}

// ---------------- GEMM: C[M,N] = act(A[M,lda(:K)] @ W[N,K]^T + bias) + res
// ACT: 0=none 1=relu 2=softplus
#define BM 64
#define BN 64
#define BKK 16
template<int ACT, bool HAS_BIAS, bool HAS_RES>
__global__ void gemm_kernel(const float* __restrict__ A, int lda,
                            const float* __restrict__ W,
                            const float* __restrict__ bias,
                            const float* __restrict__ res,
                            float* __restrict__ C,
                            int M, int N, int K)
{
    __shared__ float As[BKK][BM];
    __shared__ float Ws[BKK][BN];
    int tid = threadIdx.x;
    int tx = tid & 15, ty = tid >> 4;
    int m0 = blockIdx.y * BM, n0 = blockIdx.x * BN;

    float acc[4][4];
    #pragma unroll
    for (int i = 0; i < 4; i++)
        #pragma unroll
        for (int j = 0; j < 4; j++) acc[i][j] = 0.f;

    int ar = tid >> 2;            // 0..63
    int ac = (tid & 3) * 4;       // 0,4,8,12

    int nkt = (K + BKK - 1) / BKK;
    for (int kt = 0; kt < nkt; kt++) {
        int k0 = kt * BKK;
        int gm = m0 + ar;
        int gn = n0 + ar;
        #pragma unroll
        for (int j = 0; j < 4; j++) {
            int gk = k0 + ac + j;
            As[ac+j][ar] = (gm < M && gk < K) ? A[gm*lda + gk] : 0.f;
            Ws[ac+j][ar] = (gn < N && gk < K) ? W[gn*K  + gk] : 0.f;
        }
        __syncthreads();
        #pragma unroll
        for (int kk = 0; kk < BKK; kk++) {
            float a4[4], b4[4];
            #pragma unroll
            for (int i = 0; i < 4; i++) { a4[i] = As[kk][ty*4+i]; b4[i] = Ws[kk][tx*4+i]; }
            #pragma unroll
            for (int i = 0; i < 4; i++)
                #pragma unroll
                for (int j = 0; j < 4; j++) acc[i][j] = fmaf(a4[i], b4[j], acc[i][j]);
        }
        __syncthreads();
    }

    #pragma unroll
    for (int i = 0; i < 4; i++) {
        int gm = m0 + ty*4 + i;
        if (gm >= M) continue;
        #pragma unroll
        for (int j = 0; j < 4; j++) {
            int gn = n0 + tx*4 + j;
            if (gn >= N) continue;
            float v = acc[i][j];
            if (HAS_BIAS) v += bias[gn];
            if (ACT == 1) v = fmaxf(v, 0.f);
            else if (ACT == 2) v = (v > 20.f) ? v : log1pf(expf(v));
            if (HAS_RES) v += res[gm*N + gn];
            C[gm*N + gn] = v;
        }
    }
}

template<int ACT, bool HAS_BIAS, bool HAS_RES>
static void launch_gemm(const float* A, int lda, const float* W, const float* bias,
                        const float* res, float* C, int M, int N, int K)
{
    dim3 grid((N + BN - 1)/BN, (M + BM - 1)/BM);
    gemm_kernel<ACT,HAS_BIAS,HAS_RES><<<grid, 256>>>(A, lda, W, bias, res, C, M, N, K);
}

// ---------------- causal depthwise conv (k=4) + SiLU ----------------
__global__ void conv_silu_kernel(const float* __restrict__ conv_w,
                                 const float* __restrict__ conv_b)
{
    int idx = blockIdx.x * blockDim.x + threadIdx.x;
    if (idx >= ROWS*DI) return;
    int e = idx % DI;
    int row = idx / DI;
    int l = row % LL, b = row / LL;
    float acc = conv_b[e];
    #pragma unroll
    for (int k = 0; k < 4; k++) {
        int ll = l + k - 3;
        if (ll >= 0) acc = fmaf(g_xz[(b*LL + ll)*XZW + e], conv_w[e*4 + k], acc);
    }
    g_u[idx] = acc / (1.f + __expf(-acc));
}

// ---------------- selective scan: one warp per (b,d) ----------------
__global__ void scan_kernel(const float* __restrict__ A_log,
                            const float* __restrict__ Dp)
{
    int wid = (blockIdx.x * blockDim.x + threadIdx.x) >> 5;
    int lane = threadIdx.x & 31;
    int b = wid / DI;
    int d = wid % DI;
    if (b >= BB) return;

    float Av[4], h[4];
    #pragma unroll
    for (int i = 0; i < 4; i++) {
        Av[i] = -expf(A_log[d*DS + lane + 32*i]);
        h[i] = 0.f;
    }
    float Dpd = Dp[d];

    for (int l = 0; l < LL; l++) {
        int row = b*LL + l;
        float dt = g_dt[row*DI + d];
        float u  = g_u [row*DI + d];
        float dtu = dt * u;
        float acc = 0.f;
        #pragma unroll
        for (int i = 0; i < 4; i++) {
            float Bm = g_dbl[row*DBLW + DTR + lane + 32*i];
            float Cm = g_dbl[row*DBLW + DTR + DS + lane + 32*i];
            float dA = __expf(dt * Av[i]);
            h[i] = fmaf(dA, h[i], dtu * Bm);
            acc  = fmaf(h[i], Cm, acc);
        }
        #pragma unroll
        for (int off = 16; off > 0; off >>= 1)
            acc += __shfl_xor_sync(0xffffffffu, acc, off);
        if (lane == 0) {
            float y = acc + u * Dpd;
            float z = g_xz[row*XZW + DI + d];
            float sz = z / (1.f + __expf(-z));
            g_yact[row*DI + d] = y * sz;
        }
    }
}

// ---------------- fused attention: block per (b,h,q), 128 threads ----------------
__global__ void attn_kernel()
{
    int qi = blockIdx.x, hh = blockIdx.y, b = blockIdx.z;
    int t = threadIdx.x;
    __shared__ float qs[DK];
    __shared__ float sc[LM];
    __shared__ float red[128];

    int qrow = b*LL + qi;
    if (t < DK) qs[t] = g_q[qrow*DM + hh*DK + t];
    __syncthreads();

    float svals[4];
    float lmax = -1e30f;
    #pragma unroll
    for (int i = 0; i < 4; i++) {
        int kk = t + i*128;
        const float* kp = &g_k[(b*LM + kk)*DM + hh*DK];
        float s = 0.f;
        #pragma unroll
        for (int dd = 0; dd < DK; dd++) s = fmaf(qs[dd], kp[dd], s);
        s *= 0.17677669529663687f;   // 1/sqrt(32)
        svals[i] = s;
        lmax = fmaxf(lmax, s);
    }
    red[t] = lmax; __syncthreads();
    #pragma unroll
    for (int s = 64; s > 0; s >>= 1) { if (t < s) red[t] = fmaxf(red[t], red[t+s]); __syncthreads(); }
    float m = red[0];
    __syncthreads();

    float lsum = 0.f;
    #pragma unroll
    for (int i = 0; i < 4; i++) {
        float e = __expf(svals[i] - m);
        sc[t + i*128] = e;
        lsum += e;
    }
    red[t] = lsum; __syncthreads();
    #pragma unroll
    for (int s = 64; s > 0; s >>= 1) { if (t < s) red[t] += red[t+s]; __syncthreads(); }
    float inv = 1.f / red[0];
    __syncthreads();

    int dd = t & 31, part = t >> 5;
    float acc = 0.f;
    int kbase = part * 128;
    #pragma unroll 4
    for (int kk = kbase; kk < kbase + 128; kk++)
        acc = fmaf(sc[kk], g_v[(b*LM + kk)*DM + hh*DK + dd], acc);
    red[t] = acc; __syncthreads();
    if (t < 32) {
        float r = (red[t] + red[t+32] + red[t+64] + red[t+96]) * inv;
        g_att[qrow*DM + hh*DK + t] = r;
    }
}

// ---------------- host orchestration ----------------
extern "C" void kernel_launch(void* const* d_in, const int* in_sizes, int n_in,
                              void* d_out, int out_size)
{
    const float* x          = (const float*)d_in[0];
    const float* memory     = (const float*)d_in[1];
    // d_in[2] src_mask (all true), d_in[3] tgt_mask (unused)
    const float* in_proj_w  = (const float*)d_in[4];
    const float* conv_w     = (const float*)d_in[5];
    const float* conv_b     = (const float*)d_in[6];
    const float* x_proj_w   = (const float*)d_in[7];
    const float* dt_proj_w  = (const float*)d_in[8];
    const float* dt_proj_b  = (const float*)d_in[9];
    const float* A_log      = (const float*)d_in[10];
    const float* Dp         = (const float*)d_in[11];
    const float* out_proj_w = (const float*)d_in[12];
    const float* norm1_a    = (const float*)d_in[13];
    const float* norm1_b    = (const float*)d_in[14];
    const float* norm2_a    = (const float*)d_in[15];
    const float* norm2_b    = (const float*)d_in[16];
    const float* norm3_a    = (const float*)d_in[17];
    const float* norm3_b    = (const float*)d_in[18];
    const float* wq_w       = (const float*)d_in[19];
    const float* wq_b       = (const float*)d_in[20];
    const float* wk_w       = (const float*)d_in[21];
    const float* wk_b       = (const float*)d_in[22];
    const float* wv_w       = (const float*)d_in[23];
    const float* wv_b       = (const float*)d_in[24];
    const float* wo_w       = (const float*)d_in[25];
    const float* wo_b       = (const float*)d_in[26];
    const float* w1_w       = (const float*)d_in[27];
    const float* w1_b       = (const float*)d_in[28];
    const float* w2_w       = (const float*)d_in[29];
    const float* w2_b       = (const float*)d_in[30];
    float* out = (float*)d_out;

    float *p_ln, *p_xz, *p_u, *p_dbl, *p_dt, *p_yact, *p_h, *p_h2;
    float *p_q, *p_k, *p_v, *p_att, *p_ffh;
    cudaGetSymbolAddress((void**)&p_ln,   g_ln);
    cudaGetSymbolAddress((void**)&p_xz,   g_xz);
    cudaGetSymbolAddress((void**)&p_u,    g_u);
    cudaGetSymbolAddress((void**)&p_dbl,  g_dbl);
    cudaGetSymbolAddress((void**)&p_dt,   g_dt);
    cudaGetSymbolAddress((void**)&p_yact, g_yact);
    cudaGetSymbolAddress((void**)&p_h,    g_h);
    cudaGetSymbolAddress((void**)&p_h2,   g_h2);
    cudaGetSymbolAddress((void**)&p_q,    g_q);
    cudaGetSymbolAddress((void**)&p_k,    g_k);
    cudaGetSymbolAddress((void**)&p_v,    g_v);
    cudaGetSymbolAddress((void**)&p_att,  g_att);
    cudaGetSymbolAddress((void**)&p_ffh,  g_ffh);

    // ---- Mamba block ----
    ln_kernel<<<ROWS, DM>>>(x, norm1_a, norm1_b, p_ln);
    // xz = ln1 @ in_proj_w^T  (1024 x 2048)
    launch_gemm<0,false,false>(p_ln, DM, in_proj_w, nullptr, nullptr, p_xz, ROWS, XZW, DM);
    // u = silu(causal_conv(xi))
    conv_silu_kernel<<<(ROWS*DI+255)/256, 256>>>(conv_w, conv_b);
    // dbl = u @ x_proj_w^T  (1024 x 272)
    launch_gemm<0,false,false>(p_u, DI, x_proj_w, nullptr, nullptr, p_dbl, ROWS, DBLW, DI);
    // dt = softplus(dbl[:, :16] @ dt_proj_w^T + dt_proj_b)  (1024 x 1024)
    launch_gemm<2,true,false>(p_dbl, DBLW, dt_proj_w, dt_proj_b, nullptr, p_dt, ROWS, DI, DTR);
    // selective scan + (y + u*Dp)*silu(z)
    scan_kernel<<<(BB*DI)/8, 256>>>(A_log, Dp);
    // h = x + yact @ out_proj_w^T
    launch_gemm<0,false,true>(p_yact, DI, out_proj_w, nullptr, x, p_h, ROWS, DM, DI);

    // ---- Cross attention ----
    ln_kernel<<<ROWS, DM>>>(p_h, norm2_a, norm2_b, p_ln);
    launch_gemm<0,true,false>(p_ln,    DM, wq_w, wq_b, nullptr, p_q, ROWS, DM, DM);
    launch_gemm<0,true,false>(memory,  DM, wk_w, wk_b, nullptr, p_k, BB*LM, DM, DM);
    launch_gemm<0,true,false>(memory,  DM, wv_w, wv_b, nullptr, p_v, BB*LM, DM, DM);
    {
        dim3 grid(LL, NH, BB);
        attn_kernel<<<grid, 128>>>();
    }
    // h2 = h + att @ wo_w^T + wo_b
    launch_gemm<0,true,true>(p_att, DM, wo_w, wo_b, p_h, p_h2, ROWS, DM, DM);

    // ---- FFN ----
    ln_kernel<<<ROWS, DM>>>(p_h2, norm3_a, norm3_b, p_ln);
    launch_gemm<1,true,false>(p_ln, DM, w1_w, w1_b, nullptr, p_ffh, ROWS, DFF, DM);
    launch_gemm<0,true,true>(p_ffh, DFF, w2_w, w2_b, p_h2, out, ROWS, DM, DFF);
}

// round 2
// speedup vs baseline: 1.1340x; 1.1340x over previous
#include <cuda_runtime.h>
#include <cuda_bf16.h>
#include <math.h>

// Problem constants
#define BB 2
#define LL 512
#define LM 512
#define DM 256
#define DI 1024
#define DS 128
#define DTR 16
#define NH 8
#define DK 32
#define DFF 1024
#define ROWS (BB*LL)          // 1024
#define XZW (2*DI)            // 2048
#define DBLW (DTR + 2*DS)     // 272

// ---------------- scratch (device globals, no allocation) ----------------
__device__ float g_ln  [ROWS*DM];
__device__ float g_xz  [ROWS*XZW];
__device__ float g_u   [ROWS*DI];
__device__ float g_dbl [ROWS*DBLW];
__device__ float g_dt  [ROWS*DI];
__device__ float g_yact[ROWS*DI];
__device__ float g_h   [ROWS*DM];
__device__ float g_h2  [ROWS*DM];
__device__ float g_q   [ROWS*DM];
__device__ float g_k   [ROWS*DM];
__device__ float g_v   [ROWS*DM];
__device__ float g_att [ROWS*DM];
__device__ float g_ffh [ROWS*DFF];

// ---------------- LayerNorm: one block (256 thr) per row ----------------
__global__ void ln_kernel(const float* __restrict__ x,
                          const float* __restrict__ a,
                          const float* __restrict__ b,
                          float* __restrict__ out)
{
    int row = blockIdx.x;
    int t = threadIdx.x;
    float v = x[row*DM + t];
    __shared__ float red[DM];
    red[t] = v; __syncthreads();
    #pragma unroll
    for (int s = 128; s > 0; s >>= 1) { if (t < s) red[t] += red[t+s]; __syncthreads(); }
    float mean = red[0] * (1.0f/DM);
    __syncthreads();
    float dx = v - mean;
    red[t] = dx*dx; __syncthreads();
    #pragma unroll
    for (int s = 128; s > 0; s >>= 1) { if (t < s) red[t] += red[t+s]; __syncthreads(); }
    float var = red[0] * (1.0f/(DM-1));
    float stdv = sqrtf(var);
    out[row*DM + t] = a[t]*dx/(stdv + 1e-6f) + b[t];
}

// =======================================================================
//  Tiled SGEMM: C[M,N] = act(A[M,lda(:K)] @ W[N,K]^T + bias) + res
//  float4 global loads, register-prefetch pipeline, per-shape tile config.
//  ACT: 0=none 1=relu 2=softplus
// =======================================================================
template<int BMt,int BNt,int BKt,int TMt,int TNt,int ACT,bool BIAS,bool RES,bool NG>
__global__ __launch_bounds__(256)
void sgemm(const float* __restrict__ A, int lda,
           const float* __restrict__ W,
           const float* __restrict__ bias,
           const float* __restrict__ res,
           float* __restrict__ C, int M, int N, int K)
{
    constexpr int TX = BNt / TNt;       // threads along n
    constexpr int TY = BMt / TMt;       // threads along m
    static_assert(TX * TY == 256, "256 threads");
    constexpr int KF  = BKt / 4;        // float4 per k-row
    constexpr int AF4 = BMt * KF;       // float4 in A tile
    constexpr int WF4 = BNt * KF;       // float4 in W tile
    constexpr int AIT = (AF4 + 255) / 256;
    constexpr int WIT = (WF4 + 255) / 256;

    __shared__ float As[BKt][BMt + 4];
    __shared__ float Ws[BKt][BNt + 4];

    int tid = threadIdx.x;
    int tx = tid % TX, ty = tid / TX;
    int m0 = blockIdx.y * BMt, n0 = blockIdx.x * BNt;

    float acc[TMt][TNt];
    #pragma unroll
    for (int i = 0; i < TMt; i++)
        #pragma unroll
        for (int j = 0; j < TNt; j++) acc[i][j] = 0.f;

    float4 arg[AIT], wrg[WIT];

    // ---- fetch global -> regs for k-tile starting at k0 ----
    auto fetch = [&](int k0) {
        #pragma unroll
        for (int it = 0; it < AIT; it++) {
            int idx = tid + it * 256;
            if ((AF4 % 256 == 0) || idx < AF4) {
                int m = idx / KF, kc = (idx % KF) * 4;
                arg[it] = *(const float4*)&A[(m0 + m) * lda + k0 + kc];
            }
        }
        #pragma unroll
        for (int it = 0; it < WIT; it++) {
            int idx = tid + it * 256;
            if ((WF4 % 256 == 0) || idx < WF4) {
                int n = idx / KF, kc = (idx % KF) * 4;
                if (!NG || (n0 + n) < N)
                    wrg[it] = *(const float4*)&W[(n0 + n) * K + k0 + kc];
                else
                    wrg[it] = make_float4(0.f, 0.f, 0.f, 0.f);
            }
        }
    };
    // ---- regs -> smem (transposed) ----
    auto stash = [&]() {
        #pragma unroll
        for (int it = 0; it < AIT; it++) {
            int idx = tid + it * 256;
            if ((AF4 % 256 == 0) || idx < AF4) {
                int m = idx / KF, kc = (idx % KF) * 4;
                As[kc + 0][m] = arg[it].x;
                As[kc + 1][m] = arg[it].y;
                As[kc + 2][m] = arg[it].z;
                As[kc + 3][m] = arg[it].w;
            }
        }
        #pragma unroll
        for (int it = 0; it < WIT; it++) {
            int idx = tid + it * 256;
            if ((WF4 % 256 == 0) || idx < WF4) {
                int n = idx / KF, kc = (idx % KF) * 4;
                Ws[kc + 0][n] = wrg[it].x;
                Ws[kc + 1][n] = wrg[it].y;
                Ws[kc + 2][n] = wrg[it].z;
                Ws[kc + 3][n] = wrg[it].w;
            }
        }
    };

    int nkt = K / BKt;
    fetch(0);
    for (int kt = 0; kt < nkt; kt++) {
        __syncthreads();
        stash();
        __syncthreads();
        if (kt + 1 < nkt) fetch((kt + 1) * BKt);
        #pragma unroll
        for (int kk = 0; kk < BKt; kk++) {
            float a[TMt], b[TNt];
            #pragma unroll
            for (int i = 0; i < TMt; i++) a[i] = As[kk][ty * TMt + i];
            #pragma unroll
            for (int j = 0; j < TNt; j++) b[j] = Ws[kk][tx * TNt + j];
            #pragma unroll
            for (int i = 0; i < TMt; i++)
                #pragma unroll
                for (int j = 0; j < TNt; j++)
                    acc[i][j] = fmaf(a[i], b[j], acc[i][j]);
        }
    }

    #pragma unroll
    for (int i = 0; i < TMt; i++) {
        int gm = m0 + ty * TMt + i;
        #pragma unroll
        for (int j = 0; j < TNt; j++) {
            int gn = n0 + tx * TNt + j;
            if (NG && gn >= N) continue;
            float v = acc[i][j];
            if (BIAS) v += bias[gn];
            if (ACT == 1) v = fmaxf(v, 0.f);
            else if (ACT == 2) v = (v > 20.f) ? v : log1pf(expf(v));
            if (RES) v += res[gm * N + gn];
            C[gm * N + gn] = v;
        }
    }
}

template<int BMt,int BNt,int BKt,int TMt,int TNt,int ACT,bool BIAS,bool RES,bool NG>
static void launch_sgemm(const float* A, int lda, const float* W, const float* bias,
                         const float* res, float* C, int M, int N, int K)
{
    dim3 grid((N + BNt - 1) / BNt, (M + BMt - 1) / BMt);
    sgemm<BMt,BNt,BKt,TMt,TNt,ACT,BIAS,RES,NG><<<grid, 256>>>(A, lda, W, bias, res, C, M, N, K);
}

// ---------------- causal depthwise conv (k=4) + SiLU ----------------
__global__ void conv_silu_kernel(const float* __restrict__ conv_w,
                                 const float* __restrict__ conv_b)
{
    int idx = blockIdx.x * blockDim.x + threadIdx.x;
    if (idx >= ROWS*DI) return;
    int e = idx % DI;
    int row = idx / DI;
    int l = row % LL, b = row / LL;
    float acc = conv_b[e];
    #pragma unroll
    for (int k = 0; k < 4; k++) {
        int ll = l + k - 3;
        if (ll >= 0) acc = fmaf(g_xz[(b*LL + ll)*XZW + e], conv_w[e*4 + k], acc);
    }
    g_u[idx] = acc / (1.f + __expf(-acc));
}

// ---------------- selective scan: one warp per (b,d) ----------------
__global__ void scan_kernel(const float* __restrict__ A_log,
                            const float* __restrict__ Dp)
{
    int wid = (blockIdx.x * blockDim.x + threadIdx.x) >> 5;
    int lane = threadIdx.x & 31;
    int b = wid / DI;
    int d = wid % DI;
    if (b >= BB) return;

    float Av[4], h[4];
    #pragma unroll
    for (int i = 0; i < 4; i++) {
        Av[i] = -expf(A_log[d*DS + lane + 32*i]);
        h[i] = 0.f;
    }
    float Dpd = Dp[d];

    for (int l = 0; l < LL; l++) {
        int row = b*LL + l;
        float dt = g_dt[row*DI + d];
        float u  = g_u [row*DI + d];
        float dtu = dt * u;
        float acc = 0.f;
        #pragma unroll
        for (int i = 0; i < 4; i++) {
            float Bm = g_dbl[row*DBLW + DTR + lane + 32*i];
            float Cm = g_dbl[row*DBLW + DTR + DS + lane + 32*i];
            float dA = __expf(dt * Av[i]);
            h[i] = fmaf(dA, h[i], dtu * Bm);
            acc  = fmaf(h[i], Cm, acc);
        }
        #pragma unroll
        for (int off = 16; off > 0; off >>= 1)
            acc += __shfl_xor_sync(0xffffffffu, acc, off);
        if (lane == 0) {
            float y = acc + u * Dpd;
            float z = g_xz[row*XZW + DI + d];
            float sz = z / (1.f + __expf(-z));
            g_yact[row*DI + d] = y * sz;
        }
    }
}

// ---------------- fused attention: block per (b,h,q), 128 threads ----------------
__global__ void attn_kernel()
{
    int qi = blockIdx.x, hh = blockIdx.y, b = blockIdx.z;
    int t = threadIdx.x;
    __shared__ float qs[DK];
    __shared__ float sc[LM];
    __shared__ float red[128];

    int qrow = b*LL + qi;
    if (t < DK) qs[t] = g_q[qrow*DM + hh*DK + t];
    __syncthreads();

    float svals[4];
    float lmax = -1e30f;
    #pragma unroll
    for (int i = 0; i < 4; i++) {
        int kk = t + i*128;
        const float* kp = &g_k[(b*LM + kk)*DM + hh*DK];
        float s = 0.f;
        #pragma unroll
        for (int dd = 0; dd < DK; dd++) s = fmaf(qs[dd], kp[dd], s);
        s *= 0.17677669529663687f;   // 1/sqrt(32)
        svals[i] = s;
        lmax = fmaxf(lmax, s);
    }
    red[t] = lmax; __syncthreads();
    #pragma unroll
    for (int s = 64; s > 0; s >>= 1) { if (t < s) red[t] = fmaxf(red[t], red[t+s]); __syncthreads(); }
    float m = red[0];
    __syncthreads();

    float lsum = 0.f;
    #pragma unroll
    for (int i = 0; i < 4; i++) {
        float e = __expf(svals[i] - m);
        sc[t + i*128] = e;
        lsum += e;
    }
    red[t] = lsum; __syncthreads();
    #pragma unroll
    for (int s = 64; s > 0; s >>= 1) { if (t < s) red[t] += red[t+s]; __syncthreads(); }
    float inv = 1.f / red[0];
    __syncthreads();

    int dd = t & 31, part = t >> 5;
    float acc = 0.f;
    int kbase = part * 128;
    #pragma unroll 4
    for (int kk = kbase; kk < kbase + 128; kk++)
        acc = fmaf(sc[kk], g_v[(b*LM + kk)*DM + hh*DK + dd], acc);
    red[t] = acc; __syncthreads();
    if (t < 32) {
        float r = (red[t] + red[t+32] + red[t+64] + red[t+96]) * inv;
        g_att[qrow*DM + hh*DK + t] = r;
    }
}

// ---------------- host orchestration ----------------
extern "C" void kernel_launch(void* const* d_in, const int* in_sizes, int n_in,
                              void* d_out, int out_size)
{
    const float* x          = (const float*)d_in[0];
    const float* memory     = (const float*)d_in[1];
    // d_in[2] src_mask (all true), d_in[3] tgt_mask (unused)
    const float* in_proj_w  = (const float*)d_in[4];
    const float* conv_w     = (const float*)d_in[5];
    const float* conv_b     = (const float*)d_in[6];
    const float* x_proj_w   = (const float*)d_in[7];
    const float* dt_proj_w  = (const float*)d_in[8];
    const float* dt_proj_b  = (const float*)d_in[9];
    const float* A_log      = (const float*)d_in[10];
    const float* Dp         = (const float*)d_in[11];
    const float* out_proj_w = (const float*)d_in[12];
    const float* norm1_a    = (const float*)d_in[13];
    const float* norm1_b    = (const float*)d_in[14];
    const float* norm2_a    = (const float*)d_in[15];
    const float* norm2_b    = (const float*)d_in[16];
    const float* norm3_a    = (const float*)d_in[17];
    const float* norm3_b    = (const float*)d_in[18];
    const float* wq_w       = (const float*)d_in[19];
    const float* wq_b       = (const float*)d_in[20];
    const float* wk_w       = (const float*)d_in[21];
    const float* wk_b       = (const float*)d_in[22];
    const float* wv_w       = (const float*)d_in[23];
    const float* wv_b       = (const float*)d_in[24];
    const float* wo_w       = (const float*)d_in[25];
    const float* wo_b       = (const float*)d_in[26];
    const float* w1_w       = (const float*)d_in[27];
    const float* w1_b       = (const float*)d_in[28];
    const float* w2_w       = (const float*)d_in[29];
    const float* w2_b       = (const float*)d_in[30];
    float* out = (float*)d_out;

    float *p_ln, *p_xz, *p_u, *p_dbl, *p_dt, *p_yact, *p_h, *p_h2;
    float *p_q, *p_k, *p_v, *p_att, *p_ffh;
    cudaGetSymbolAddress((void**)&p_ln,   g_ln);
    cudaGetSymbolAddress((void**)&p_xz,   g_xz);
    cudaGetSymbolAddress((void**)&p_u,    g_u);
    cudaGetSymbolAddress((void**)&p_dbl,  g_dbl);
    cudaGetSymbolAddress((void**)&p_dt,   g_dt);
    cudaGetSymbolAddress((void**)&p_yact, g_yact);
    cudaGetSymbolAddress((void**)&p_h,    g_h);
    cudaGetSymbolAddress((void**)&p_h2,   g_h2);
    cudaGetSymbolAddress((void**)&p_q,    g_q);
    cudaGetSymbolAddress((void**)&p_k,    g_k);
    cudaGetSymbolAddress((void**)&p_v,    g_v);
    cudaGetSymbolAddress((void**)&p_att,  g_att);
    cudaGetSymbolAddress((void**)&p_ffh,  g_ffh);

    // ---- Mamba block ----
    ln_kernel<<<ROWS, DM>>>(x, norm1_a, norm1_b, p_ln);
    // xz = ln1 @ in_proj_w^T  (1024 x 2048 x 256): 128x128 tiles -> 128 blocks
    launch_sgemm<128,128,16,8,8, 0,false,false,false>(p_ln, DM, in_proj_w, nullptr, nullptr, p_xz, ROWS, XZW, DM);
    // u = silu(causal_conv(xi))
    conv_silu_kernel<<<(ROWS*DI+255)/256, 256>>>(conv_w, conv_b);
    // dbl = u @ x_proj_w^T  (1024 x 272 x 1024): 64x64 tiles -> 80 blocks (N-guard)
    launch_sgemm<64,64,16,4,4, 0,false,false,true>(p_u, DI, x_proj_w, nullptr, nullptr, p_dbl, ROWS, DBLW, DI);
    // dt = softplus(dbl[:, :16] @ dt_proj_w^T + b)  (1024 x 1024 x 16): 256 blocks
    launch_sgemm<64,64,16,4,4, 2,true,false,false>(p_dbl, DBLW, dt_proj_w, dt_proj_b, nullptr, p_dt, ROWS, DI, DTR);
    // selective scan + (y + u*Dp)*silu(z)
    scan_kernel<<<(BB*DI)/8, 256>>>(A_log, Dp);
    // h = x + yact @ out_proj_w^T  (1024 x 256 x 1024): 64x32 tiles -> 128 blocks
    launch_sgemm<64,32,16,4,2, 0,false,true,false>(p_yact, DI, out_proj_w, nullptr, x, p_h, ROWS, DM, DI);

    // ---- Cross attention ----
    ln_kernel<<<ROWS, DM>>>(p_h, norm2_a, norm2_b, p_ln);
    launch_sgemm<64,32,16,4,2, 0,true,false,false>(p_ln,   DM, wq_w, wq_b, nullptr, p_q, ROWS, DM, DM);
    launch_sgemm<64,32,16,4,2, 0,true,false,false>(memory, DM, wk_w, wk_b, nullptr, p_k, BB*LM, DM, DM);
    launch_sgemm<64,32,16,4,2, 0,true,false,false>(memory, DM, wv_w, wv_b, nullptr, p_v, BB*LM, DM, DM);
    {
        dim3 grid(LL, NH, BB);
        attn_kernel<<<grid, 128>>>();
    }
    // h2 = h + att @ wo_w^T + wo_b
    launch_sgemm<64,32,16,4,2, 0,true,true,false>(p_att, DM, wo_w, wo_b, p_h, p_h2, ROWS, DM, DM);

    // ---- FFN ----
    ln_kernel<<<ROWS, DM>>>(p_h2, norm3_a, norm3_b, p_ln);
    // FF1 (1024 x 1024 x 256): 64x128 tiles -> 128 blocks
    launch_sgemm<64,128,16,4,8, 1,true,false,false>(p_ln, DM, w1_w, w1_b, nullptr, p_ffh, ROWS, DFF, DM);
    // FF2 (1024 x 256 x 1024): 64x32 tiles -> 128 blocks
    launch_sgemm<64,32,16,4,2, 0,true,true,false>(p_ffh, DFF, w2_w, w2_b, p_h2, out, ROWS, DM, DFF);
}

// round 3
// speedup vs baseline: 1.7485x; 1.5420x over previous
#include <cuda_runtime.h>
#include <cuda_bf16.h>
#include <math.h>

// Problem constants
#define BB 2
#define LL 512
#define LM 512
#define DM 256
#define DI 1024
#define DS 128
#define DTR 16
#define NH 8
#define DK 32
#define DFF 1024
#define ROWS (BB*LL)          // 1024
#define XZW (2*DI)            // 2048
#define DBLW (DTR + 2*DS)     // 272
#define NBH (BB*NH)           // 16

// ---------------- scratch (device globals, no allocation) ----------------
__device__ float g_ln  [ROWS*DM];
__device__ float g_xz  [ROWS*XZW];
__device__ float g_u   [ROWS*DI];
__device__ float g_dbl [ROWS*DBLW];
__device__ float g_dt  [ROWS*DI];
__device__ float g_yact[ROWS*DI];
__device__ float g_h   [ROWS*DM];
__device__ float g_h2  [ROWS*DM];
__device__ float g_q   [ROWS*DM];
__device__ float g_k   [ROWS*DM];
__device__ float g_v   [ROWS*DM];
__device__ float g_att [ROWS*DM];
__device__ float g_ffh [ROWS*DFF];
__device__ float g_sc  [NBH*LL*LM];   // 16 MB attention scores

// ---------------- LayerNorm: one block (256 thr) per row ----------------
__global__ void ln_kernel(const float* __restrict__ x,
                          const float* __restrict__ a,
                          const float* __restrict__ b,
                          float* __restrict__ out)
{
    int row = blockIdx.x;
    int t = threadIdx.x;
    float v = x[row*DM + t];
    __shared__ float red[DM];
    red[t] = v; __syncthreads();
    #pragma unroll
    for (int s = 128; s > 0; s >>= 1) { if (t < s) red[t] += red[t+s]; __syncthreads(); }
    float mean = red[0] * (1.0f/DM);
    __syncthreads();
    float dx = v - mean;
    red[t] = dx*dx; __syncthreads();
    #pragma unroll
    for (int s = 128; s > 0; s >>= 1) { if (t < s) red[t] += red[t+s]; __syncthreads(); }
    float var = red[0] * (1.0f/(DM-1));
    float stdv = sqrtf(var);
    out[row*DM + t] = a[t]*dx/(stdv + 1e-6f) + b[t];
}

// =======================================================================
//  Double-buffered tiled SGEMM: C = act(A[M,lda(:K)] @ W[N,K]^T + bias) + res
//  ACT: 0=none 1=relu 2=softplus
// =======================================================================
template<int BMt,int BNt,int BKt,int TMt,int TNt,int ACT,bool BIAS,bool RES,bool NG>
__global__ __launch_bounds__(256)
void sgemm(const float* __restrict__ A, int lda,
           const float* __restrict__ W,
           const float* __restrict__ bias,
           const float* __restrict__ res,
           float* __restrict__ C, int M, int N, int K)
{
    constexpr int TX = BNt / TNt;
    constexpr int TY = BMt / TMt;
    static_assert(TX * TY == 256, "256 threads");
    constexpr int KF  = BKt / 4;
    constexpr int AF4 = BMt * KF;
    constexpr int WF4 = BNt * KF;
    constexpr int AIT = (AF4 + 255) / 256;
    constexpr int WIT = (WF4 + 255) / 256;

    __shared__ float As[2][BKt][BMt + 4];
    __shared__ float Ws[2][BKt][BNt + 4];

    int tid = threadIdx.x;
    int tx = tid % TX, ty = tid / TX;
    int m0 = blockIdx.y * BMt, n0 = blockIdx.x * BNt;

    float acc[TMt][TNt];
    #pragma unroll
    for (int i = 0; i < TMt; i++)
        #pragma unroll
        for (int j = 0; j < TNt; j++) acc[i][j] = 0.f;

    float4 arg[AIT], wrg[WIT];

    auto fetch = [&](int k0) {
        #pragma unroll
        for (int it = 0; it < AIT; it++) {
            int idx = tid + it * 256;
            if ((AF4 % 256 == 0) || idx < AF4) {
                int m = idx / KF, kc = (idx % KF) * 4;
                arg[it] = *(const float4*)&A[(m0 + m) * lda + k0 + kc];
            }
        }
        #pragma unroll
        for (int it = 0; it < WIT; it++) {
            int idx = tid + it * 256;
            if ((WF4 % 256 == 0) || idx < WF4) {
                int n = idx / KF, kc = (idx % KF) * 4;
                if (!NG || (n0 + n) < N)
                    wrg[it] = *(const float4*)&W[(n0 + n) * K + k0 + kc];
                else
                    wrg[it] = make_float4(0.f, 0.f, 0.f, 0.f);
            }
        }
    };
    auto stash = [&](int buf) {
        #pragma unroll
        for (int it = 0; it < AIT; it++) {
            int idx = tid + it * 256;
            if ((AF4 % 256 == 0) || idx < AF4) {
                int m = idx / KF, kc = (idx % KF) * 4;
                As[buf][kc + 0][m] = arg[it].x;
                As[buf][kc + 1][m] = arg[it].y;
                As[buf][kc + 2][m] = arg[it].z;
                As[buf][kc + 3][m] = arg[it].w;
            }
        }
        #pragma unroll
        for (int it = 0; it < WIT; it++) {
            int idx = tid + it * 256;
            if ((WF4 % 256 == 0) || idx < WF4) {
                int n = idx / KF, kc = (idx % KF) * 4;
                Ws[buf][kc + 0][n] = wrg[it].x;
                Ws[buf][kc + 1][n] = wrg[it].y;
                Ws[buf][kc + 2][n] = wrg[it].z;
                Ws[buf][kc + 3][n] = wrg[it].w;
            }
        }
    };

    int nkt = K / BKt;
    fetch(0);
    stash(0);
    __syncthreads();
    int cur = 0;
    for (int kt = 0; kt < nkt; kt++) {
        if (kt + 1 < nkt) fetch((kt + 1) * BKt);
        #pragma unroll
        for (int kk = 0; kk < BKt; kk++) {
            float a[TMt], b[TNt];
            #pragma unroll
            for (int i = 0; i < TMt; i++) a[i] = As[cur][kk][ty * TMt + i];
            #pragma unroll
            for (int j = 0; j < TNt; j++) b[j] = Ws[cur][kk][tx * TNt + j];
            #pragma unroll
            for (int i = 0; i < TMt; i++)
                #pragma unroll
                for (int j = 0; j < TNt; j++)
                    acc[i][j] = fmaf(a[i], b[j], acc[i][j]);
        }
        if (kt + 1 < nkt) {
            stash(cur ^ 1);
            __syncthreads();
            cur ^= 1;
        }
    }

    #pragma unroll
    for (int i = 0; i < TMt; i++) {
        int gm = m0 + ty * TMt + i;
        #pragma unroll
        for (int j = 0; j < TNt; j++) {
            int gn = n0 + tx * TNt + j;
            if (NG && gn >= N) continue;
            float v = acc[i][j];
            if (BIAS) v += bias[gn];
            if (ACT == 1) v = fmaxf(v, 0.f);
            else if (ACT == 2) v = (v > 20.f) ? v : log1pf(expf(v));
            if (RES) v += res[gm * N + gn];
            C[gm * N + gn] = v;
        }
    }
}

template<int BMt,int BNt,int BKt,int TMt,int TNt,int ACT,bool BIAS,bool RES,bool NG>
static void launch_sgemm(const float* A, int lda, const float* W, const float* bias,
                         const float* res, float* C, int M, int N, int K)
{
    dim3 grid((N + BNt - 1) / BNt, (M + BMt - 1) / BMt);
    sgemm<BMt,BNt,BKt,TMt,TNt,ACT,BIAS,RES,NG><<<grid, 256>>>(A, lda, W, bias, res, C, M, N, K);
}

// ---------------- causal depthwise conv (k=4) + SiLU ----------------
__global__ void conv_silu_kernel(const float* __restrict__ conv_w,
                                 const float* __restrict__ conv_b)
{
    int idx = blockIdx.x * blockDim.x + threadIdx.x;
    if (idx >= ROWS*DI) return;
    int e = idx % DI;
    int row = idx / DI;
    int l = row % LL, b = row / LL;
    float acc = conv_b[e];
    #pragma unroll
    for (int k = 0; k < 4; k++) {
        int ll = l + k - 3;
        if (ll >= 0) acc = fmaf(g_xz[(b*LL + ll)*XZW + e], conv_w[e*4 + k], acc);
    }
    g_u[idx] = acc / (1.f + __expf(-acc));
}

// ---------------- selective scan: one warp per (b,d) ----------------
__global__ void scan_kernel(const float* __restrict__ A_log,
                            const float* __restrict__ Dp)
{
    int wid = (blockIdx.x * blockDim.x + threadIdx.x) >> 5;
    int lane = threadIdx.x & 31;
    int b = wid / DI;
    int d = wid % DI;
    if (b >= BB) return;

    float Av[4], h[4];
    #pragma unroll
    for (int i = 0; i < 4; i++) {
        Av[i] = -expf(A_log[d*DS + lane + 32*i]);
        h[i] = 0.f;
    }
    float Dpd = Dp[d];

    for (int l = 0; l < LL; l++) {
        int row = b*LL + l;
        float dt = g_dt[row*DI + d];
        float u  = g_u [row*DI + d];
        float dtu = dt * u;
        float acc = 0.f;
        #pragma unroll
        for (int i = 0; i < 4; i++) {
            float Bm = g_dbl[row*DBLW + DTR + lane + 32*i];
            float Cm = g_dbl[row*DBLW + DTR + DS + lane + 32*i];
            float dA = __expf(dt * Av[i]);
            h[i] = fmaf(dA, h[i], dtu * Bm);
            acc  = fmaf(h[i], Cm, acc);
        }
        #pragma unroll
        for (int off = 16; off > 0; off >>= 1)
            acc += __shfl_xor_sync(0xffffffffu, acc, off);
        if (lane == 0) {
            float y = acc + u * Dpd;
            float z = g_xz[row*XZW + DI + d];
            float sz = z / (1.f + __expf(-z));
            g_yact[row*DI + d] = y * sz;
        }
    }
}

// ---------------- attention: batched score GEMM ----------------
// grid (k-tile 8, q-tile 8, bh 16), 256 thr. scores[bh][q][k] = Q.K^T * scale
__global__ __launch_bounds__(256) void score_gemm()
{
    int bh = blockIdx.z, b = bh >> 3, h = bh & 7;
    int q0 = blockIdx.y * 64, k0 = blockIdx.x * 64;
    int tid = threadIdx.x;
    __shared__ float Qs[DK][68];
    __shared__ float Ks[DK][68];

    #pragma unroll
    for (int it = 0; it < 2; it++) {
        int f4i = tid + it * 256;          // 512 float4 per tile
        int r = f4i >> 3, c = (f4i & 7) * 4;
        float4 qv = *(const float4*)&g_q[(b*LL + q0 + r)*DM + h*DK + c];
        float4 kv = *(const float4*)&g_k[(b*LM + k0 + r)*DM + h*DK + c];
        Qs[c+0][r] = qv.x; Qs[c+1][r] = qv.y; Qs[c+2][r] = qv.z; Qs[c+3][r] = qv.w;
        Ks[c+0][r] = kv.x; Ks[c+1][r] = kv.y; Ks[c+2][r] = kv.z; Ks[c+3][r] = kv.w;
    }
    __syncthreads();

    int tx = tid & 15, ty = tid >> 4;
    float acc[4][4];
    #pragma unroll
    for (int i = 0; i < 4; i++)
        #pragma unroll
        for (int j = 0; j < 4; j++) acc[i][j] = 0.f;

    #pragma unroll
    for (int d = 0; d < DK; d++) {
        float a[4], bt[4];
        #pragma unroll
        for (int i = 0; i < 4; i++) { a[i] = Qs[d][ty*4+i]; bt[i] = Ks[d][tx*4+i]; }
        #pragma unroll
        for (int i = 0; i < 4; i++)
            #pragma unroll
            for (int j = 0; j < 4; j++) acc[i][j] = fmaf(a[i], bt[j], acc[i][j]);
    }

    const float scale = 0.17677669529663687f;
    #pragma unroll
    for (int i = 0; i < 4; i++) {
        long rowo = (long)(bh*LL + q0 + ty*4 + i) * LM;
        #pragma unroll
        for (int j = 0; j < 4; j++)
            g_sc[rowo + k0 + tx*4 + j] = acc[i][j] * scale;
    }
}

// ---------------- softmax over each score row (512) ----------------
__global__ __launch_bounds__(128) void softmax_kernel()
{
    int row = blockIdx.x;
    int t = threadIdx.x;
    float4* p = (float4*)&g_sc[(long)row * LM];
    float4 v = p[t];
    float m = fmaxf(fmaxf(v.x, v.y), fmaxf(v.z, v.w));
    __shared__ float red[128];
    red[t] = m; __syncthreads();
    #pragma unroll
    for (int s = 64; s > 0; s >>= 1) { if (t < s) red[t] = fmaxf(red[t], red[t+s]); __syncthreads(); }
    m = red[0]; __syncthreads();
    v.x = __expf(v.x - m); v.y = __expf(v.y - m);
    v.z = __expf(v.z - m); v.w = __expf(v.w - m);
    red[t] = v.x + v.y + v.z + v.w; __syncthreads();
    #pragma unroll
    for (int s = 64; s > 0; s >>= 1) { if (t < s) red[t] += red[t+s]; __syncthreads(); }
    float inv = 1.f / red[0];
    v.x *= inv; v.y *= inv; v.z *= inv; v.w *= inv;
    p[t] = v;
}

// ---------------- batched PV GEMM: att = P @ V ----------------
// grid (q-tile 8, bh 16), 256 thr. Each block: 64 q x 32 d.
__global__ __launch_bounds__(256) void pv_gemm()
{
    int bh = blockIdx.y, b = bh >> 3, h = bh & 7;
    int q0 = blockIdx.x * 64;
    int tid = threadIdx.x;
    int tx = tid & 7, ty = tid >> 3;     // tx: d/4, ty: q/2

    __shared__ float Ps[64][68];
    __shared__ float Vs[64][36];

    float acc[2][4];
    #pragma unroll
    for (int i = 0; i < 2; i++)
        #pragma unroll
        for (int j = 0; j < 4; j++) acc[i][j] = 0.f;

    for (int kt = 0; kt < 8; kt++) {
        int k0 = kt * 64;
        #pragma unroll
        for (int it = 0; it < 4; it++) {   // P tile: 64x64 = 1024 f4
            int f4i = tid + it * 256;
            int r = f4i >> 4, c = (f4i & 15) * 4;
            float4 pv = *(const float4*)&g_sc[(long)(bh*LL + q0 + r)*LM + k0 + c];
            *(float4*)&Ps[r][c] = pv;
        }
        #pragma unroll
        for (int it = 0; it < 2; it++) {   // V tile: 64x32 = 512 f4
            int f4i = tid + it * 256;
            int r = f4i >> 3, c = (f4i & 7) * 4;
            float4 vv = *(const float4*)&g_v[(b*LM + k0 + r)*DM + h*DK + c];
            *(float4*)&Vs[r][c] = vv;
        }
        __syncthreads();
        #pragma unroll
        for (int kk = 0; kk < 64; kk++) {
            float pv0 = Ps[ty*2+0][kk];
            float pv1 = Ps[ty*2+1][kk];
            float vv[4];
            #pragma unroll
            for (int j = 0; j < 4; j++) vv[j] = Vs[kk][tx*4+j];
            #pragma unroll
            for (int j = 0; j < 4; j++) {
                acc[0][j] = fmaf(pv0, vv[j], acc[0][j]);
                acc[1][j] = fmaf(pv1, vv[j], acc[1][j]);
            }
        }
        __syncthreads();
    }

    #pragma unroll
    for (int i = 0; i < 2; i++) {
        int q = q0 + ty*2 + i;
        #pragma unroll
        for (int j = 0; j < 4; j++)
            g_att[(b*LL + q)*DM + h*DK + tx*4 + j] = acc[i][j];
    }
}

// ---------------- host orchestration ----------------
extern "C" void kernel_launch(void* const* d_in, const int* in_sizes, int n_in,
                              void* d_out, int out_size)
{
    const float* x          = (const float*)d_in[0];
    const float* memory     = (const float*)d_in[1];
    // d_in[2] src_mask (all true), d_in[3] tgt_mask (unused)
    const float* in_proj_w  = (const float*)d_in[4];
    const float* conv_w     = (const float*)d_in[5];
    const float* conv_b     = (const float*)d_in[6];
    const float* x_proj_w   = (const float*)d_in[7];
    const float* dt_proj_w  = (const float*)d_in[8];
    const float* dt_proj_b  = (const float*)d_in[9];
    const float* A_log      = (const float*)d_in[10];
    const float* Dp         = (const float*)d_in[11];
    const float* out_proj_w = (const float*)d_in[12];
    const float* norm1_a    = (const float*)d_in[13];
    const float* norm1_b    = (const float*)d_in[14];
    const float* norm2_a    = (const float*)d_in[15];
    const float* norm2_b    = (const float*)d_in[16];
    const float* norm3_a    = (const float*)d_in[17];
    const float* norm3_b    = (const float*)d_in[18];
    const float* wq_w       = (const float*)d_in[19];
    const float* wq_b       = (const float*)d_in[20];
    const float* wk_w       = (const float*)d_in[21];
    const float* wk_b       = (const float*)d_in[22];
    const float* wv_w       = (const float*)d_in[23];
    const float* wv_b       = (const float*)d_in[24];
    const float* wo_w       = (const float*)d_in[25];
    const float* wo_b       = (const float*)d_in[26];
    const float* w1_w       = (const float*)d_in[27];
    const float* w1_b       = (const float*)d_in[28];
    const float* w2_w       = (const float*)d_in[29];
    const float* w2_b       = (const float*)d_in[30];
    float* out = (float*)d_out;

    float *p_ln, *p_xz, *p_u, *p_dbl, *p_dt, *p_yact, *p_h, *p_h2;
    float *p_q, *p_k, *p_v, *p_att, *p_ffh;
    cudaGetSymbolAddress((void**)&p_ln,   g_ln);
    cudaGetSymbolAddress((void**)&p_xz,   g_xz);
    cudaGetSymbolAddress((void**)&p_u,    g_u);
    cudaGetSymbolAddress((void**)&p_dbl,  g_dbl);
    cudaGetSymbolAddress((void**)&p_dt,   g_dt);
    cudaGetSymbolAddress((void**)&p_yact, g_yact);
    cudaGetSymbolAddress((void**)&p_h,    g_h);
    cudaGetSymbolAddress((void**)&p_h2,   g_h2);
    cudaGetSymbolAddress((void**)&p_q,    g_q);
    cudaGetSymbolAddress((void**)&p_k,    g_k);
    cudaGetSymbolAddress((void**)&p_v,    g_v);
    cudaGetSymbolAddress((void**)&p_att,  g_att);
    cudaGetSymbolAddress((void**)&p_ffh,  g_ffh);

    // ---- Mamba block ----
    ln_kernel<<<ROWS, DM>>>(x, norm1_a, norm1_b, p_ln);
    // xz = ln1 @ in_proj_w^T  (1024 x 2048 x 256): 64x128 -> 256 blocks
    launch_sgemm<64,128,16,4,8, 0,false,false,false>(p_ln, DM, in_proj_w, nullptr, nullptr, p_xz, ROWS, XZW, DM);
    // u = silu(causal_conv(xi))
    conv_silu_kernel<<<(ROWS*DI+255)/256, 256>>>(conv_w, conv_b);
    // dbl = u @ x_proj_w^T  (1024 x 272 x 1024): 32x64 -> 160 blocks (N-guard)
    launch_sgemm<32,64,16,2,4, 0,false,false,true>(p_u, DI, x_proj_w, nullptr, nullptr, p_dbl, ROWS, DBLW, DI);
    // dt = softplus(dbl[:, :16] @ dt_proj_w^T + b)  (1024 x 1024 x 16): 256 blocks
    launch_sgemm<64,64,16,4,4, 2,true,false,false>(p_dbl, DBLW, dt_proj_w, dt_proj_b, nullptr, p_dt, ROWS, DI, DTR);
    // selective scan + (y + u*Dp)*silu(z)
    scan_kernel<<<(BB*DI)/8, 256>>>(A_log, Dp);
    // h = x + yact @ out_proj_w^T  (1024 x 256 x 1024): 64x32 -> 128 blocks
    launch_sgemm<64,32,16,4,2, 0,false,true,false>(p_yact, DI, out_proj_w, nullptr, x, p_h, ROWS, DM, DI);

    // ---- Cross attention ----
    ln_kernel<<<ROWS, DM>>>(p_h, norm2_a, norm2_b, p_ln);
    launch_sgemm<64,32,16,4,2, 0,true,false,false>(p_ln,   DM, wq_w, wq_b, nullptr, p_q, ROWS, DM, DM);
    launch_sgemm<64,32,16,4,2, 0,true,false,false>(memory, DM, wk_w, wk_b, nullptr, p_k, BB*LM, DM, DM);
    launch_sgemm<64,32,16,4,2, 0,true,false,false>(memory, DM, wv_w, wv_b, nullptr, p_v, BB*LM, DM, DM);
    {
        dim3 sgrid(LM/64, LL/64, NBH);
        score_gemm<<<sgrid, 256>>>();
        softmax_kernel<<<NBH*LL, 128>>>();
        dim3 pgrid(LL/64, NBH);
        pv_gemm<<<pgrid, 256>>>();
    }
    // h2 = h + att @ wo_w^T + wo_b
    launch_sgemm<64,32,16,4,2, 0,true,true,false>(p_att, DM, wo_w, wo_b, p_h, p_h2, ROWS, DM, DM);

    // ---- FFN ----
    ln_kernel<<<ROWS, DM>>>(p_h2, norm3_a, norm3_b, p_ln);
    // FF1 (1024 x 1024 x 256): 64x64 -> 256 blocks
    launch_sgemm<64,64,16,4,4, 1,true,false,false>(p_ln, DM, w1_w, w1_b, nullptr, p_ffh, ROWS, DFF, DM);
    // FF2 (1024 x 256 x 1024): 64x32 -> 128 blocks
    launch_sgemm<64,32,16,4,2, 0,true,true,false>(p_ffh, DFF, w2_w, w2_b, p_h2, out, ROWS, DM, DFF);
}

// round 4
// speedup vs baseline: 2.0184x; 1.1543x over previous
#include <cuda_runtime.h>
#include <cuda_bf16.h>
#include <math.h>
#include <stdint.h>

// Problem constants
#define BB 2
#define LL 512
#define LM 512
#define DM 256
#define DI 1024
#define DS 128
#define DTR 16
#define NH 8
#define DK 32
#define DFF 1024
#define ROWS (BB*LL)          // 1024
#define XZW (2*DI)            // 2048
#define DBLW (DTR + 2*DS)     // 272
#define NBH (BB*NH)           // 16

// ---------------- scratch (device globals, no allocation) ----------------
__device__ float g_ln  [ROWS*DM];
__device__ float g_xz  [ROWS*XZW];
__device__ float g_u   [ROWS*DI];
__device__ float g_dbl [ROWS*DBLW];
__device__ float g_dt  [ROWS*DI];
__device__ float g_yact[ROWS*DI];
__device__ float g_h   [ROWS*DM];
__device__ float g_h2  [ROWS*DM];
__device__ float g_q   [ROWS*DM];
__device__ float g_k   [ROWS*DM];
__device__ float g_v   [ROWS*DM];
__device__ float g_att [ROWS*DM];
__device__ float g_ffh [ROWS*DFF];
__device__ float g_sc  [NBH*LL*LM];   // 16 MB attention scores

// ---------------- LayerNorm: one block (256 thr) per row ----------------
__global__ void ln_kernel(const float* __restrict__ x,
                          const float* __restrict__ a,
                          const float* __restrict__ b,
                          float* __restrict__ out)
{
    int row = blockIdx.x;
    int t = threadIdx.x;
    float v = x[row*DM + t];
    __shared__ float red[DM];
    red[t] = v; __syncthreads();
    #pragma unroll
    for (int s = 128; s > 0; s >>= 1) { if (t < s) red[t] += red[t+s]; __syncthreads(); }
    float mean = red[0] * (1.0f/DM);
    __syncthreads();
    float dx = v - mean;
    red[t] = dx*dx; __syncthreads();
    #pragma unroll
    for (int s = 128; s > 0; s >>= 1) { if (t < s) red[t] += red[t+s]; __syncthreads(); }
    float var = red[0] * (1.0f/(DM-1));
    float stdv = sqrtf(var);
    out[row*DM + t] = a[t]*dx/(stdv + 1e-6f) + b[t];
}

// tf32 round-to-nearest
__device__ __forceinline__ float to_tf32(float x) {
    uint32_t r;
    asm("cvt.rna.tf32.f32 %0, %1;" : "=r"(r) : "f"(x));
    return __uint_as_float(r);
}

// =======================================================================
//  TF32 tensor-core GEMM: C = act(A[M,lda(:K)] @ W[N,K]^T + bias) + res
//  mma.sync.m16n8k8 tf32, double-buffered smem, warp-tiled.
//  ACT: 0=none 1=relu 2=softplus
// =======================================================================
template<int BM,int BN,int BK,int WM,int WN,int ACT,bool BIAS,bool RES,bool NG>
__global__ __launch_bounds__(WM*WN*32)
void tgemm(const float* __restrict__ A, int lda,
           const float* __restrict__ W,
           const float* __restrict__ bias,
           const float* __restrict__ res,
           float* __restrict__ C, int M, int N, int K)
{
    constexpr int NT  = WM*WN*32;
    constexpr int TM  = BM/WM;          // warp tile m
    constexpr int TN  = BN/WN;          // warp tile n
    constexpr int MF  = TM/16;          // m frags per warp
    constexpr int NF  = TN/8;           // n frags per warp
    constexpr int KF  = BK/4;           // float4 per k-row
    constexpr int AF4 = BM*KF;
    constexpr int WF4 = BN*KF;
    constexpr int AIT = (AF4+NT-1)/NT;
    constexpr int WIT = (WF4+NT-1)/NT;
    // pads chosen so (BM+8)%32==8 and (BN+8)%32==8 -> conflict-free frag loads
    __shared__ float As[2][BK][BM+8];
    __shared__ float Ws[2][BK][BN+8];

    int tid = threadIdx.x;
    int wid = tid >> 5, lane = tid & 31;
    int wm = wid % WM, wn = wid / WM;
    int gid = lane >> 2, tig = lane & 3;
    int m0 = blockIdx.y * BM, n0 = blockIdx.x * BN;

    float c[MF][NF][4];
    #pragma unroll
    for (int mi = 0; mi < MF; mi++)
        #pragma unroll
        for (int ni = 0; ni < NF; ni++)
            #pragma unroll
            for (int r = 0; r < 4; r++) c[mi][ni][r] = 0.f;

    float4 arg[AIT], wrg[WIT];

    auto fetch = [&](int k0) {
        #pragma unroll
        for (int it = 0; it < AIT; it++) {
            int idx = tid + it * NT;
            if ((AF4 % NT == 0) || idx < AF4) {
                int m = idx / KF, kc = (idx % KF) * 4;
                arg[it] = *(const float4*)&A[(m0 + m) * lda + k0 + kc];
            }
        }
        #pragma unroll
        for (int it = 0; it < WIT; it++) {
            int idx = tid + it * NT;
            if ((WF4 % NT == 0) || idx < WF4) {
                int n = idx / KF, kc = (idx % KF) * 4;
                if (!NG || (n0 + n) < N)
                    wrg[it] = *(const float4*)&W[(n0 + n) * K + k0 + kc];
                else
                    wrg[it] = make_float4(0.f, 0.f, 0.f, 0.f);
            }
        }
    };
    auto stash = [&](int buf) {
        #pragma unroll
        for (int it = 0; it < AIT; it++) {
            int idx = tid + it * NT;
            if ((AF4 % NT == 0) || idx < AF4) {
                int m = idx / KF, kc = (idx % KF) * 4;
                As[buf][kc + 0][m] = to_tf32(arg[it].x);
                As[buf][kc + 1][m] = to_tf32(arg[it].y);
                As[buf][kc + 2][m] = to_tf32(arg[it].z);
                As[buf][kc + 3][m] = to_tf32(arg[it].w);
            }
        }
        #pragma unroll
        for (int it = 0; it < WIT; it++) {
            int idx = tid + it * NT;
            if ((WF4 % NT == 0) || idx < WF4) {
                int n = idx / KF, kc = (idx % KF) * 4;
                Ws[buf][kc + 0][n] = to_tf32(wrg[it].x);
                Ws[buf][kc + 1][n] = to_tf32(wrg[it].y);
                Ws[buf][kc + 2][n] = to_tf32(wrg[it].z);
                Ws[buf][kc + 3][n] = to_tf32(wrg[it].w);
            }
        }
    };

    int nkt = K / BK;
    fetch(0);
    stash(0);
    __syncthreads();
    int cur = 0;
    for (int kt = 0; kt < nkt; kt++) {
        if (kt + 1 < nkt) fetch((kt + 1) * BK);
        #pragma unroll
        for (int ks = 0; ks < BK; ks += 8) {
            uint32_t af[MF][4], bf[NF][2];
            #pragma unroll
            for (int mi = 0; mi < MF; mi++) {
                int mb = wm * TM + mi * 16;
                af[mi][0] = __float_as_uint(As[cur][ks + tig    ][mb + gid    ]);
                af[mi][1] = __float_as_uint(As[cur][ks + tig    ][mb + gid + 8]);
                af[mi][2] = __float_as_uint(As[cur][ks + tig + 4][mb + gid    ]);
                af[mi][3] = __float_as_uint(As[cur][ks + tig + 4][mb + gid + 8]);
            }
            #pragma unroll
            for (int ni = 0; ni < NF; ni++) {
                int nb = wn * TN + ni * 8;
                bf[ni][0] = __float_as_uint(Ws[cur][ks + tig    ][nb + gid]);
                bf[ni][1] = __float_as_uint(Ws[cur][ks + tig + 4][nb + gid]);
            }
            #pragma unroll
            for (int mi = 0; mi < MF; mi++)
                #pragma unroll
                for (int ni = 0; ni < NF; ni++) {
                    asm volatile(
                        "mma.sync.aligned.m16n8k8.row.col.f32.tf32.tf32.f32 "
                        "{%0,%1,%2,%3}, {%4,%5,%6,%7}, {%8,%9}, {%0,%1,%2,%3};"
                        : "+f"(c[mi][ni][0]), "+f"(c[mi][ni][1]),
                          "+f"(c[mi][ni][2]), "+f"(c[mi][ni][3])
                        : "r"(af[mi][0]), "r"(af[mi][1]), "r"(af[mi][2]), "r"(af[mi][3]),
                          "r"(bf[ni][0]), "r"(bf[ni][1]));
                }
        }
        if (kt + 1 < nkt) {
            stash(cur ^ 1);
            __syncthreads();
            cur ^= 1;
        }
    }

    // epilogue: c0,c1 -> row gid, cols tig*2, tig*2+1; c2,c3 -> row gid+8
    #pragma unroll
    for (int mi = 0; mi < MF; mi++)
        #pragma unroll
        for (int ni = 0; ni < NF; ni++)
            #pragma unroll
            for (int h = 0; h < 2; h++) {
                int gm = m0 + wm * TM + mi * 16 + gid + h * 8;
                int gn = n0 + wn * TN + ni * 8 + tig * 2;
                #pragma unroll
                for (int e = 0; e < 2; e++) {
                    int col = gn + e;
                    if (NG && col >= N) continue;
                    float v = c[mi][ni][h * 2 + e];
                    if (BIAS) v += bias[col];
                    if (ACT == 1) v = fmaxf(v, 0.f);
                    else if (ACT == 2) v = (v > 20.f) ? v : log1pf(expf(v));
                    if (RES) v += res[gm * N + col];
                    C[gm * N + col] = v;
                }
            }
}

template<int BM,int BN,int BK,int WM,int WN,int ACT,bool BIAS,bool RES,bool NG>
static void launch_tgemm(const float* A, int lda, const float* W, const float* bias,
                         const float* res, float* C, int M, int N, int K)
{
    dim3 grid((N + BN - 1) / BN, M / BM);
    tgemm<BM,BN,BK,WM,WN,ACT,BIAS,RES,NG><<<grid, WM*WN*32>>>(A, lda, W, bias, res, C, M, N, K);
}

// ---------------- causal depthwise conv (k=4) + SiLU ----------------
__global__ void conv_silu_kernel(const float* __restrict__ conv_w,
                                 const float* __restrict__ conv_b)
{
    int idx = blockIdx.x * blockDim.x + threadIdx.x;
    if (idx >= ROWS*DI) return;
    int e = idx % DI;
    int row = idx / DI;
    int l = row % LL, b = row / LL;
    float acc = conv_b[e];
    #pragma unroll
    for (int k = 0; k < 4; k++) {
        int ll = l + k - 3;
        if (ll >= 0) acc = fmaf(g_xz[(b*LL + ll)*XZW + e], conv_w[e*4 + k], acc);
    }
    g_u[idx] = acc / (1.f + __expf(-acc));
}

// ---------------- selective scan: one warp per (b,d) ----------------
__global__ void scan_kernel(const float* __restrict__ A_log,
                            const float* __restrict__ Dp)
{
    int wid = (blockIdx.x * blockDim.x + threadIdx.x) >> 5;
    int lane = threadIdx.x & 31;
    int b = wid / DI;
    int d = wid % DI;
    if (b >= BB) return;

    float Av[4], h[4];
    #pragma unroll
    for (int i = 0; i < 4; i++) {
        Av[i] = -expf(A_log[d*DS + lane + 32*i]);
        h[i] = 0.f;
    }
    float Dpd = Dp[d];

    for (int l = 0; l < LL; l++) {
        int row = b*LL + l;
        float dt = g_dt[row*DI + d];
        float u  = g_u [row*DI + d];
        float dtu = dt * u;
        float acc = 0.f;
        #pragma unroll
        for (int i = 0; i < 4; i++) {
            float Bm = g_dbl[row*DBLW + DTR + lane + 32*i];
            float Cm = g_dbl[row*DBLW + DTR + DS + lane + 32*i];
            float dA = __expf(dt * Av[i]);
            h[i] = fmaf(dA, h[i], dtu * Bm);
            acc  = fmaf(h[i], Cm, acc);
        }
        #pragma unroll
        for (int off = 16; off > 0; off >>= 1)
            acc += __shfl_xor_sync(0xffffffffu, acc, off);
        if (lane == 0) {
            float y = acc + u * Dpd;
            float z = g_xz[row*XZW + DI + d];
            float sz = z / (1.f + __expf(-z));
            g_yact[row*DI + d] = y * sz;
        }
    }
}

// ---------------- attention: batched score GEMM ----------------
__global__ __launch_bounds__(256) void score_gemm()
{
    int bh = blockIdx.z, b = bh >> 3, h = bh & 7;
    int q0 = blockIdx.y * 64, k0 = blockIdx.x * 64;
    int tid = threadIdx.x;
    __shared__ float Qs[DK][68];
    __shared__ float Ks[DK][68];

    #pragma unroll
    for (int it = 0; it < 2; it++) {
        int f4i = tid + it * 256;
        int r = f4i >> 3, c = (f4i & 7) * 4;
        float4 qv = *(const float4*)&g_q[(b*LL + q0 + r)*DM + h*DK + c];
        float4 kv = *(const float4*)&g_k[(b*LM + k0 + r)*DM + h*DK + c];
        Qs[c+0][r] = qv.x; Qs[c+1][r] = qv.y; Qs[c+2][r] = qv.z; Qs[c+3][r] = qv.w;
        Ks[c+0][r] = kv.x; Ks[c+1][r] = kv.y; Ks[c+2][r] = kv.z; Ks[c+3][r] = kv.w;
    }
    __syncthreads();

    int tx = tid & 15, ty = tid >> 4;
    float acc[4][4];
    #pragma unroll
    for (int i = 0; i < 4; i++)
        #pragma unroll
        for (int j = 0; j < 4; j++) acc[i][j] = 0.f;

    #pragma unroll
    for (int d = 0; d < DK; d++) {
        float a[4], bt[4];
        #pragma unroll
        for (int i = 0; i < 4; i++) { a[i] = Qs[d][ty*4+i]; bt[i] = Ks[d][tx*4+i]; }
        #pragma unroll
        for (int i = 0; i < 4; i++)
            #pragma unroll
            for (int j = 0; j < 4; j++) acc[i][j] = fmaf(a[i], bt[j], acc[i][j]);
    }

    const float scale = 0.17677669529663687f;
    #pragma unroll
    for (int i = 0; i < 4; i++) {
        long rowo = (long)(bh*LL + q0 + ty*4 + i) * LM;
        #pragma unroll
        for (int j = 0; j < 4; j++)
            g_sc[rowo + k0 + tx*4 + j] = acc[i][j] * scale;
    }
}

// ---------------- softmax over each score row (512) ----------------
__global__ __launch_bounds__(128) void softmax_kernel()
{
    int row = blockIdx.x;
    int t = threadIdx.x;
    float4* p = (float4*)&g_sc[(long)row * LM];
    float4 v = p[t];
    float m = fmaxf(fmaxf(v.x, v.y), fmaxf(v.z, v.w));
    __shared__ float red[128];
    red[t] = m; __syncthreads();
    #pragma unroll
    for (int s = 64; s > 0; s >>= 1) { if (t < s) red[t] = fmaxf(red[t], red[t+s]); __syncthreads(); }
    m = red[0]; __syncthreads();
    v.x = __expf(v.x - m); v.y = __expf(v.y - m);
    v.z = __expf(v.z - m); v.w = __expf(v.w - m);
    red[t] = v.x + v.y + v.z + v.w; __syncthreads();
    #pragma unroll
    for (int s = 64; s > 0; s >>= 1) { if (t < s) red[t] += red[t+s]; __syncthreads(); }
    float inv = 1.f / red[0];
    v.x *= inv; v.y *= inv; v.z *= inv; v.w *= inv;
    p[t] = v;
}

// ---------------- batched PV GEMM: att = P @ V ----------------
__global__ __launch_bounds__(256) void pv_gemm()
{
    int bh = blockIdx.y, b = bh >> 3, h = bh & 7;
    int q0 = blockIdx.x * 64;
    int tid = threadIdx.x;
    int tx = tid & 7, ty = tid >> 3;

    __shared__ float Ps[64][68];
    __shared__ float Vs[64][36];

    float acc[2][4];
    #pragma unroll
    for (int i = 0; i < 2; i++)
        #pragma unroll
        for (int j = 0; j < 4; j++) acc[i][j] = 0.f;

    for (int kt = 0; kt < 8; kt++) {
        int k0 = kt * 64;
        #pragma unroll
        for (int it = 0; it < 4; it++) {
            int f4i = tid + it * 256;
            int r = f4i >> 4, c = (f4i & 15) * 4;
            float4 pv = *(const float4*)&g_sc[(long)(bh*LL + q0 + r)*LM + k0 + c];
            *(float4*)&Ps[r][c] = pv;
        }
        #pragma unroll
        for (int it = 0; it < 2; it++) {
            int f4i = tid + it * 256;
            int r = f4i >> 3, c = (f4i & 7) * 4;
            float4 vv = *(const float4*)&g_v[(b*LM + k0 + r)*DM + h*DK + c];
            *(float4*)&Vs[r][c] = vv;
        }
        __syncthreads();
        #pragma unroll
        for (int kk = 0; kk < 64; kk++) {
            float pv0 = Ps[ty*2+0][kk];
            float pv1 = Ps[ty*2+1][kk];
            float vv[4];
            #pragma unroll
            for (int j = 0; j < 4; j++) vv[j] = Vs[kk][tx*4+j];
            #pragma unroll
            for (int j = 0; j < 4; j++) {
                acc[0][j] = fmaf(pv0, vv[j], acc[0][j]);
                acc[1][j] = fmaf(pv1, vv[j], acc[1][j]);
            }
        }
        __syncthreads();
    }

    #pragma unroll
    for (int i = 0; i < 2; i++) {
        int q = q0 + ty*2 + i;
        #pragma unroll
        for (int j = 0; j < 4; j++)
            g_att[(b*LL + q)*DM + h*DK + tx*4 + j] = acc[i][j];
    }
}

// ---------------- host orchestration ----------------
extern "C" void kernel_launch(void* const* d_in, const int* in_sizes, int n_in,
                              void* d_out, int out_size)
{
    const float* x          = (const float*)d_in[0];
    const float* memory     = (const float*)d_in[1];
    // d_in[2] src_mask (all true), d_in[3] tgt_mask (unused)
    const float* in_proj_w  = (const float*)d_in[4];
    const float* conv_w     = (const float*)d_in[5];
    const float* conv_b     = (const float*)d_in[6];
    const float* x_proj_w   = (const float*)d_in[7];
    const float* dt_proj_w  = (const float*)d_in[8];
    const float* dt_proj_b  = (const float*)d_in[9];
    const float* A_log      = (const float*)d_in[10];
    const float* Dp         = (const float*)d_in[11];
    const float* out_proj_w = (const float*)d_in[12];
    const float* norm1_a    = (const float*)d_in[13];
    const float* norm1_b    = (const float*)d_in[14];
    const float* norm2_a    = (const float*)d_in[15];
    const float* norm2_b    = (const float*)d_in[16];
    const float* norm3_a    = (const float*)d_in[17];
    const float* norm3_b    = (const float*)d_in[18];
    const float* wq_w       = (const float*)d_in[19];
    const float* wq_b       = (const float*)d_in[20];
    const float* wk_w       = (const float*)d_in[21];
    const float* wk_b       = (const float*)d_in[22];
    const float* wv_w       = (const float*)d_in[23];
    const float* wv_b       = (const float*)d_in[24];
    const float* wo_w       = (const float*)d_in[25];
    const float* wo_b       = (const float*)d_in[26];
    const float* w1_w       = (const float*)d_in[27];
    const float* w1_b       = (const float*)d_in[28];
    const float* w2_w       = (const float*)d_in[29];
    const float* w2_b       = (const float*)d_in[30];
    float* out = (float*)d_out;

    float *p_ln, *p_xz, *p_u, *p_dbl, *p_dt, *p_yact, *p_h, *p_h2;
    float *p_q, *p_k, *p_v, *p_att, *p_ffh;
    cudaGetSymbolAddress((void**)&p_ln,   g_ln);
    cudaGetSymbolAddress((void**)&p_xz,   g_xz);
    cudaGetSymbolAddress((void**)&p_u,    g_u);
    cudaGetSymbolAddress((void**)&p_dbl,  g_dbl);
    cudaGetSymbolAddress((void**)&p_dt,   g_dt);
    cudaGetSymbolAddress((void**)&p_yact, g_yact);
    cudaGetSymbolAddress((void**)&p_h,    g_h);
    cudaGetSymbolAddress((void**)&p_h2,   g_h2);
    cudaGetSymbolAddress((void**)&p_q,    g_q);
    cudaGetSymbolAddress((void**)&p_k,    g_k);
    cudaGetSymbolAddress((void**)&p_v,    g_v);
    cudaGetSymbolAddress((void**)&p_att,  g_att);
    cudaGetSymbolAddress((void**)&p_ffh,  g_ffh);

    // ---- Mamba block ----
    ln_kernel<<<ROWS, DM>>>(x, norm1_a, norm1_b, p_ln);
    // xz = ln1 @ in_proj_w^T  (1024 x 2048 x 256): 128x64 -> 256 blocks, 256 thr
    launch_tgemm<128,64,16,4,2, 0,false,false,false>(p_ln, DM, in_proj_w, nullptr, nullptr, p_xz, ROWS, XZW, DM);
    // u = silu(causal_conv(xi))
    conv_silu_kernel<<<(ROWS*DI+255)/256, 256>>>(conv_w, conv_b);
    // dbl = u @ x_proj_w^T  (1024 x 272 x 1024): 64x32 -> 144 blocks (N-guard), 128 thr
    launch_tgemm<64,32,16,2,2, 0,false,false,true>(p_u, DI, x_proj_w, nullptr, nullptr, p_dbl, ROWS, DBLW, DI);
    // dt = softplus(dbl[:, :16] @ dt_proj_w^T + b)  (1024 x 1024 x 16): 64x64 -> 256 blocks
    launch_tgemm<64,64,16,2,2, 2,true,false,false>(p_dbl, DBLW, dt_proj_w, dt_proj_b, nullptr, p_dt, ROWS, DI, DTR);
    // selective scan + (y + u*Dp)*silu(z)
    scan_kernel<<<(BB*DI)/8, 256>>>(A_log, Dp);
    // h = x + yact @ out_proj_w^T  (1024 x 256 x 1024): 64x32 -> 128 blocks
    launch_tgemm<64,32,16,2,2, 0,false,true,false>(p_yact, DI, out_proj_w, nullptr, x, p_h, ROWS, DM, DI);

    // ---- Cross attention ----
    ln_kernel<<<ROWS, DM>>>(p_h, norm2_a, norm2_b, p_ln);
    launch_tgemm<64,32,16,2,2, 0,true,false,false>(p_ln,   DM, wq_w, wq_b, nullptr, p_q, ROWS, DM, DM);
    launch_tgemm<64,32,16,2,2, 0,true,false,false>(memory, DM, wk_w, wk_b, nullptr, p_k, BB*LM, DM, DM);
    launch_tgemm<64,32,16,2,2, 0,true,false,false>(memory, DM, wv_w, wv_b, nullptr, p_v, BB*LM, DM, DM);
    {
        dim3 sgrid(LM/64, LL/64, NBH);
        score_gemm<<<sgrid, 256>>>();
        softmax_kernel<<<NBH*LL, 128>>>();
        dim3 pgrid(LL/64, NBH);
        pv_gemm<<<pgrid, 256>>>();
    }
    // h2 = h + att @ wo_w^T + wo_b
    launch_tgemm<64,32,16,2,2, 0,true,true,false>(p_att, DM, wo_w, wo_b, p_h, p_h2, ROWS, DM, DM);

    // ---- FFN ----
    ln_kernel<<<ROWS, DM>>>(p_h2, norm3_a, norm3_b, p_ln);
    // FF1 (1024 x 1024 x 256): 128x64 -> 128 blocks
    launch_tgemm<128,64,16,4,2, 1,true,false,false>(p_ln, DM, w1_w, w1_b, nullptr, p_ffh, ROWS, DFF, DM);
    // FF2 (1024 x 256 x 1024): 64x32 -> 128 blocks
    launch_tgemm<64,32,16,2,2, 0,true,true,false>(p_ffh, DFF, w2_w, w2_b, p_h2, out, ROWS, DM, DFF);
}

// round 5
// speedup vs baseline: 2.5002x; 1.2387x over previous
#include <cuda_runtime.h>
#include <cuda_bf16.h>
#include <math.h>
#include <stdint.h>

// Problem constants
#define BB 2
#define LL 512
#define LM 512
#define DM 256
#define DI 1024
#define DS 128
#define DTR 16
#define NH 8
#define DK 32
#define DFF 1024
#define ROWS (BB*LL)          // 1024
#define XZW (2*DI)            // 2048
#define DBLW (DTR + 2*DS)     // 272
#define NBH (BB*NH)           // 16
#define XP_PAD 320            // padded N stride for x_proj split-K partials

// ---------------- scratch (device globals, no allocation) ----------------
__device__ float g_ln  [ROWS*DM];
__device__ float g_xz  [ROWS*XZW];
__device__ float g_u   [ROWS*DI];
__device__ float g_dbl [ROWS*DBLW];
__device__ float g_dt  [ROWS*DI];
__device__ float g_yact[ROWS*DI];
__device__ float g_h   [ROWS*DM];
__device__ float g_h2  [ROWS*DM];
__device__ float g_q   [ROWS*DM];
__device__ float g_k   [ROWS*DM];
__device__ float g_v   [ROWS*DM];
__device__ float g_att [ROWS*DM];
__device__ float g_ffh [ROWS*DFF];
__device__ float g_sc  [NBH*LL*LM];      // 16 MB attention scores
__device__ float g_part[4*ROWS*XP_PAD];  // split-K partials (x_proj)

// ---------------- LayerNorm: one block (256 thr) per row ----------------
__global__ void ln_kernel(const float* __restrict__ x,
                          const float* __restrict__ a,
                          const float* __restrict__ b,
                          float* __restrict__ out)
{
    int row = blockIdx.x;
    int t = threadIdx.x;
    float v = x[row*DM + t];
    __shared__ float red[DM];
    red[t] = v; __syncthreads();
    #pragma unroll
    for (int s = 128; s > 0; s >>= 1) { if (t < s) red[t] += red[t+s]; __syncthreads(); }
    float mean = red[0] * (1.0f/DM);
    __syncthreads();
    float dx = v - mean;
    red[t] = dx*dx; __syncthreads();
    #pragma unroll
    for (int s = 128; s > 0; s >>= 1) { if (t < s) red[t] += red[t+s]; __syncthreads(); }
    float var = red[0] * (1.0f/(DM-1));
    float stdv = sqrtf(var);
    out[row*DM + t] = a[t]*dx/(stdv + 1e-6f) + b[t];
}

// tf32 round-to-nearest
__device__ __forceinline__ float to_tf32(float x) {
    uint32_t r;
    asm("cvt.rna.tf32.f32 %0, %1;" : "=r"(r) : "f"(x));
    return __uint_as_float(r);
}

#define MMA_TF32(C0,C1,C2,C3,A0,A1,A2,A3,B0,B1) \
    asm volatile( \
        "mma.sync.aligned.m16n8k8.row.col.f32.tf32.tf32.f32 " \
        "{%0,%1,%2,%3}, {%4,%5,%6,%7}, {%8,%9}, {%0,%1,%2,%3};" \
        : "+f"(C0), "+f"(C1), "+f"(C2), "+f"(C3) \
        : "r"(A0), "r"(A1), "r"(A2), "r"(A3), "r"(B0), "r"(B1))

// =======================================================================
//  TF32 tensor-core GEMM: C = act(A[M,lda(:K)] @ W[N,K]^T + bias) + res
//  warp tile (BM/WM)x(BN/WN); double-buffered smem, reg prefetch.
//  SPLIT>1 + PART: blockIdx.z handles K/SPLIT chunk, raw partial to C+z*M*ldc
//  ACT: 0=none 1=relu 2=softplus
// =======================================================================
template<int BM,int BN,int BK,int WM,int WN,int ACT,bool BIAS,bool RES,bool NG,
         int SPLIT,bool PART>
__global__ __launch_bounds__(WM*WN*32)
void tgemm(const float* __restrict__ A, int lda,
           const float* __restrict__ W,
           const float* __restrict__ bias,
           const float* __restrict__ res,
           float* __restrict__ C, int ldc, int M, int N, int K)
{
    constexpr int NT  = WM*WN*32;
    constexpr int TM  = BM/WM;
    constexpr int TN  = BN/WN;
    constexpr int MF  = TM/16;
    constexpr int NF  = TN/8;
    constexpr int KF  = BK/4;
    constexpr int AF4 = BM*KF;
    constexpr int WF4 = BN*KF;
    constexpr int AIT = (AF4+NT-1)/NT;
    constexpr int WIT = (WF4+NT-1)/NT;

    __shared__ float As[2][BK][BM+8];
    __shared__ float Ws[2][BK][BN+8];

    int tid = threadIdx.x;
    int wid = tid >> 5, lane = tid & 31;
    int wm = wid % WM, wn = wid / WM;
    int gid = lane >> 2, tig = lane & 3;
    int m0 = blockIdx.y * BM, n0 = blockIdx.x * BN;

    int kchunk = K / SPLIT;
    int kbase  = (SPLIT > 1) ? blockIdx.z * kchunk : 0;
    int nkt    = kchunk / BK;
    if (PART) C += (size_t)blockIdx.z * (size_t)M * ldc;

    float c[MF][NF][4];
    #pragma unroll
    for (int mi = 0; mi < MF; mi++)
        #pragma unroll
        for (int ni = 0; ni < NF; ni++)
            #pragma unroll
            for (int r = 0; r < 4; r++) c[mi][ni][r] = 0.f;

    float4 arg[AIT], wrg[WIT];

    auto fetch = [&](int k0) {
        #pragma unroll
        for (int it = 0; it < AIT; it++) {
            int idx = tid + it * NT;
            if ((AF4 % NT == 0) || idx < AF4) {
                int m = idx / KF, kc = (idx % KF) * 4;
                arg[it] = *(const float4*)&A[(m0 + m) * lda + k0 + kc];
            }
        }
        #pragma unroll
        for (int it = 0; it < WIT; it++) {
            int idx = tid + it * NT;
            if ((WF4 % NT == 0) || idx < WF4) {
                int n = idx / KF, kc = (idx % KF) * 4;
                if (!NG || (n0 + n) < N)
                    wrg[it] = *(const float4*)&W[(n0 + n) * K + k0 + kc];
                else
                    wrg[it] = make_float4(0.f, 0.f, 0.f, 0.f);
            }
        }
    };
    auto stash = [&](int buf) {
        #pragma unroll
        for (int it = 0; it < AIT; it++) {
            int idx = tid + it * NT;
            if ((AF4 % NT == 0) || idx < AF4) {
                int m = idx / KF, kc = (idx % KF) * 4;
                As[buf][kc + 0][m] = to_tf32(arg[it].x);
                As[buf][kc + 1][m] = to_tf32(arg[it].y);
                As[buf][kc + 2][m] = to_tf32(arg[it].z);
                As[buf][kc + 3][m] = to_tf32(arg[it].w);
            }
        }
        #pragma unroll
        for (int it = 0; it < WIT; it++) {
            int idx = tid + it * NT;
            if ((WF4 % NT == 0) || idx < WF4) {
                int n = idx / KF, kc = (idx % KF) * 4;
                Ws[buf][kc + 0][n] = to_tf32(wrg[it].x);
                Ws[buf][kc + 1][n] = to_tf32(wrg[it].y);
                Ws[buf][kc + 2][n] = to_tf32(wrg[it].z);
                Ws[buf][kc + 3][n] = to_tf32(wrg[it].w);
            }
        }
    };

    fetch(kbase);
    stash(0);
    __syncthreads();
    int cur = 0;
    for (int kt = 0; kt < nkt; kt++) {
        if (kt + 1 < nkt) fetch(kbase + (kt + 1) * BK);
        #pragma unroll
        for (int ks = 0; ks < BK; ks += 8) {
            uint32_t af[MF][4], bf[NF][2];
            #pragma unroll
            for (int mi = 0; mi < MF; mi++) {
                int mb = wm * TM + mi * 16;
                af[mi][0] = __float_as_uint(As[cur][ks + tig    ][mb + gid    ]);
                af[mi][1] = __float_as_uint(As[cur][ks + tig    ][mb + gid + 8]);
                af[mi][2] = __float_as_uint(As[cur][ks + tig + 4][mb + gid    ]);
                af[mi][3] = __float_as_uint(As[cur][ks + tig + 4][mb + gid + 8]);
            }
            #pragma unroll
            for (int ni = 0; ni < NF; ni++) {
                int nb = wn * TN + ni * 8;
                bf[ni][0] = __float_as_uint(Ws[cur][ks + tig    ][nb + gid]);
                bf[ni][1] = __float_as_uint(Ws[cur][ks + tig + 4][nb + gid]);
            }
            #pragma unroll
            for (int mi = 0; mi < MF; mi++)
                #pragma unroll
                for (int ni = 0; ni < NF; ni++)
                    MMA_TF32(c[mi][ni][0], c[mi][ni][1], c[mi][ni][2], c[mi][ni][3],
                             af[mi][0], af[mi][1], af[mi][2], af[mi][3],
                             bf[ni][0], bf[ni][1]);
        }
        if (kt + 1 < nkt) {
            stash(cur ^ 1);
            __syncthreads();
            cur ^= 1;
        }
    }

    #pragma unroll
    for (int mi = 0; mi < MF; mi++)
        #pragma unroll
        for (int ni = 0; ni < NF; ni++)
            #pragma unroll
            for (int h = 0; h < 2; h++) {
                int gm = m0 + wm * TM + mi * 16 + gid + h * 8;
                int gn = n0 + wn * TN + ni * 8 + tig * 2;
                #pragma unroll
                for (int e = 0; e < 2; e++) {
                    int col = gn + e;
                    float v = c[mi][ni][h * 2 + e];
                    if (PART) {
                        C[(size_t)gm * ldc + col] = v;   // raw partial (pad cols ok)
                    } else {
                        if (NG && col >= N) continue;
                        if (BIAS) v += bias[col];
                        if (ACT == 1) v = fmaxf(v, 0.f);
                        else if (ACT == 2) v = (v > 20.f) ? v : log1pf(expf(v));
                        if (RES) v += res[(size_t)gm * ldc + col];
                        C[(size_t)gm * ldc + col] = v;
                    }
                }
            }
}

template<int BM,int BN,int BK,int WM,int WN,int ACT,bool BIAS,bool RES,bool NG,
         int SPLIT = 1, bool PART = false>
static void launch_tgemm(const float* A, int lda, const float* W, const float* bias,
                         const float* res, float* C, int ldc, int M, int N, int K)
{
    dim3 grid((N + BN - 1) / BN, M / BM, SPLIT);
    tgemm<BM,BN,BK,WM,WN,ACT,BIAS,RES,NG,SPLIT,PART>
        <<<grid, WM*WN*32>>>(A, lda, W, bias, res, C, ldc, M, N, K);
}

// ---------------- split-K reduce for x_proj (4 partials -> g_dbl) ----------------
__global__ __launch_bounds__(256) void reduce4_x()
{
    int idx = blockIdx.x * 256 + threadIdx.x;     // over ROWS * (DBLW/4)
    if (idx >= ROWS * (DBLW/4)) return;
    int gm = idx / (DBLW/4);
    int c4 = (idx % (DBLW/4)) * 4;
    const float* base = g_part + (size_t)gm * XP_PAD + c4;
    float4 s = make_float4(0.f, 0.f, 0.f, 0.f);
    #pragma unroll
    for (int sp = 0; sp < 4; sp++) {
        float4 v = *(const float4*)(base + (size_t)sp * ROWS * XP_PAD);
        s.x += v.x; s.y += v.y; s.z += v.z; s.w += v.w;
    }
    *(float4*)&g_dbl[(size_t)gm * DBLW + c4] = s;
}

// ---------------- causal depthwise conv (k=4) + SiLU ----------------
__global__ void conv_silu_kernel(const float* __restrict__ conv_w,
                                 const float* __restrict__ conv_b)
{
    int idx = blockIdx.x * blockDim.x + threadIdx.x;
    if (idx >= ROWS*DI) return;
    int e = idx % DI;
    int row = idx / DI;
    int l = row % LL, b = row / LL;
    float acc = conv_b[e];
    #pragma unroll
    for (int k = 0; k < 4; k++) {
        int ll = l + k - 3;
        if (ll >= 0) acc = fmaf(g_xz[(b*LL + ll)*XZW + e], conv_w[e*4 + k], acc);
    }
    g_u[idx] = acc / (1.f + __expf(-acc));
}

// ---------------- selective scan: warp per (b,d), unroll-4 reductions ----------------
__global__ void scan_kernel(const float* __restrict__ A_log,
                            const float* __restrict__ Dp)
{
    int wid = (blockIdx.x * blockDim.x + threadIdx.x) >> 5;
    int lane = threadIdx.x & 31;
    int b = wid / DI;
    int d = wid % DI;
    if (b >= BB) return;

    float Av[4], h[4];
    #pragma unroll
    for (int i = 0; i < 4; i++) {
        Av[i] = -expf(A_log[d*DS + lane + 32*i]);
        h[i] = 0.f;
    }
    float Dpd = Dp[d];

    for (int l0 = 0; l0 < LL; l0 += 4) {
        float acc[4], uu[4], zz[4];
        #pragma unroll
        for (int j = 0; j < 4; j++) {
            int row = b*LL + l0 + j;
            float dt = g_dt[row*DI + d];
            uu[j] = g_u[row*DI + d];
            zz[j] = g_xz[row*XZW + DI + d];
            float dtu = dt * uu[j];
            float a = 0.f;
            #pragma unroll
            for (int i = 0; i < 4; i++) {
                float Bm = g_dbl[row*DBLW + DTR + lane + 32*i];
                float Cm = g_dbl[row*DBLW + DTR + DS + lane + 32*i];
                float dA = __expf(dt * Av[i]);
                h[i] = fmaf(dA, h[i], dtu * Bm);
                a = fmaf(h[i], Cm, a);
            }
            acc[j] = a;
        }
        #pragma unroll
        for (int off = 16; off > 0; off >>= 1) {
            #pragma unroll
            for (int j = 0; j < 4; j++)
                acc[j] += __shfl_xor_sync(0xffffffffu, acc[j], off);
        }
        #pragma unroll
        for (int j = 0; j < 4; j++) {
            if (lane == j) {
                int row = b*LL + l0 + j;
                float y = acc[j] + uu[j] * Dpd;
                float sz = zz[j] / (1.f + __expf(-zz[j]));
                g_yact[row*DI + d] = y * sz;
            }
        }
    }
}

// ---------------- attention: score = Q.K^T * scale via tf32 mma ----------------
// grid (k-tile 8, q-tile 8, bh 16), 128 thr, block 64q x 64k, K=32
__global__ __launch_bounds__(128) void score_mma()
{
    int bh = blockIdx.z, b = bh >> 3, h = bh & 7;
    int q0 = blockIdx.y * 64, k0 = blockIdx.x * 64;
    int tid = threadIdx.x;
    int wid = tid >> 5, lane = tid & 31;
    int wm = wid & 1, wn = wid >> 1;
    int gid = lane >> 2, tig = lane & 3;

    __shared__ float Qs[32][72];
    __shared__ float Ks[32][72];

    #pragma unroll
    for (int it = 0; it < 4; it++) {
        int f4i = tid + it * 128;
        int r = f4i >> 3, cc = (f4i & 7) * 4;
        float4 qv = *(const float4*)&g_q[(b*LL + q0 + r)*DM + h*DK + cc];
        float4 kv = *(const float4*)&g_k[(b*LM + k0 + r)*DM + h*DK + cc];
        Qs[cc+0][r] = to_tf32(qv.x); Qs[cc+1][r] = to_tf32(qv.y);
        Qs[cc+2][r] = to_tf32(qv.z); Qs[cc+3][r] = to_tf32(qv.w);
        Ks[cc+0][r] = to_tf32(kv.x); Ks[cc+1][r] = to_tf32(kv.y);
        Ks[cc+2][r] = to_tf32(kv.z); Ks[cc+3][r] = to_tf32(kv.w);
    }
    __syncthreads();

    float c[2][4][4];
    #pragma unroll
    for (int mi = 0; mi < 2; mi++)
        #pragma unroll
        for (int ni = 0; ni < 4; ni++)
            #pragma unroll
            for (int r = 0; r < 4; r++) c[mi][ni][r] = 0.f;

    #pragma unroll
    for (int ks = 0; ks < 32; ks += 8) {
        uint32_t af[2][4], bf[4][2];
        #pragma unroll
        for (int mi = 0; mi < 2; mi++) {
            int mb = wm * 32 + mi * 16;
            af[mi][0] = __float_as_uint(Qs[ks + tig    ][mb + gid    ]);
            af[mi][1] = __float_as_uint(Qs[ks + tig    ][mb + gid + 8]);
            af[mi][2] = __float_as_uint(Qs[ks + tig + 4][mb + gid    ]);
            af[mi][3] = __float_as_uint(Qs[ks + tig + 4][mb + gid + 8]);
        }
        #pragma unroll
        for (int ni = 0; ni < 4; ni++) {
            int nb = wn * 32 + ni * 8;
            bf[ni][0] = __float_as_uint(Ks[ks + tig    ][nb + gid]);
            bf[ni][1] = __float_as_uint(Ks[ks + tig + 4][nb + gid]);
        }
        #pragma unroll
        for (int mi = 0; mi < 2; mi++)
            #pragma unroll
            for (int ni = 0; ni < 4; ni++)
                MMA_TF32(c[mi][ni][0], c[mi][ni][1], c[mi][ni][2], c[mi][ni][3],
                         af[mi][0], af[mi][1], af[mi][2], af[mi][3],
                         bf[ni][0], bf[ni][1]);
    }

    const float scale = 0.17677669529663687f;   // 1/sqrt(32)
    #pragma unroll
    for (int mi = 0; mi < 2; mi++)
        #pragma unroll
        for (int ni = 0; ni < 4; ni++)
            #pragma unroll
            for (int hh = 0; hh < 2; hh++) {
                int gq = q0 + wm * 32 + mi * 16 + gid + hh * 8;
                int gk = k0 + wn * 32 + ni * 8 + tig * 2;
                long rowo = (long)(bh*LL + gq) * LM;
                g_sc[rowo + gk + 0] = c[mi][ni][hh*2 + 0] * scale;
                g_sc[rowo + gk + 1] = c[mi][ni][hh*2 + 1] * scale;
            }
}

// ---------------- softmax over each score row (512) ----------------
__global__ __launch_bounds__(128) void softmax_kernel()
{
    int row = blockIdx.x;
    int t = threadIdx.x;
    float4* p = (float4*)&g_sc[(long)row * LM];
    float4 v = p[t];
    float m = fmaxf(fmaxf(v.x, v.y), fmaxf(v.z, v.w));
    __shared__ float red[128];
    red[t] = m; __syncthreads();
    #pragma unroll
    for (int s = 64; s > 0; s >>= 1) { if (t < s) red[t] = fmaxf(red[t], red[t+s]); __syncthreads(); }
    m = red[0]; __syncthreads();
    v.x = __expf(v.x - m); v.y = __expf(v.y - m);
    v.z = __expf(v.z - m); v.w = __expf(v.w - m);
    red[t] = v.x + v.y + v.z + v.w; __syncthreads();
    #pragma unroll
    for (int s = 64; s > 0; s >>= 1) { if (t < s) red[t] += red[t+s]; __syncthreads(); }
    float inv = 1.f / red[0];
    v.x *= inv; v.y *= inv; v.z *= inv; v.w *= inv;
    p[t] = v;
}

// ---------------- PV via tf32 mma: att = P @ V ----------------
// grid (q-tile 8, bh 16), 128 thr, block 64q x 32d, K=512 loop BK=32
__global__ __launch_bounds__(128) void pv_mma()
{
    int bh = blockIdx.y, b = bh >> 3, h = bh & 7;
    int q0 = blockIdx.x * 64;
    int tid = threadIdx.x;
    int wid = tid >> 5, lane = tid & 31;
    int gid = lane >> 2, tig = lane & 3;

    __shared__ float Ps[2][32][72];
    __shared__ float Vs[2][32][40];

    float c[4][4];
    #pragma unroll
    for (int ni = 0; ni < 4; ni++)
        #pragma unroll
        for (int r = 0; r < 4; r++) c[ni][r] = 0.f;

    float4 parg[4], varg[2];

    auto fetch = [&](int k0) {
        #pragma unroll
        for (int it = 0; it < 4; it++) {
            int f4i = tid + it * 128;
            int r = f4i >> 3, cc = (f4i & 7) * 4;
            parg[it] = *(const float4*)&g_sc[((long)bh*LL + q0 + r)*LM + k0 + cc];
        }
        #pragma unroll
        for (int it = 0; it < 2; it++) {
            int f4i = tid + it * 128;
            int r = f4i >> 3, cc = (f4i & 7) * 4;
            varg[it] = *(const float4*)&g_v[(b*LM + k0 + r)*DM + h*DK + cc];
        }
    };
    auto stash = [&](int buf) {
        #pragma unroll
        for (int it = 0; it < 4; it++) {
            int f4i = tid + it * 128;
            int r = f4i >> 3, cc = (f4i & 7) * 4;
            Ps[buf][cc+0][r] = to_tf32(parg[it].x);
            Ps[buf][cc+1][r] = to_tf32(parg[it].y);
            Ps[buf][cc+2][r] = to_tf32(parg[it].z);
            Ps[buf][cc+3][r] = to_tf32(parg[it].w);
        }
        #pragma unroll
        for (int it = 0; it < 2; it++) {
            int f4i = tid + it * 128;
            int r = f4i >> 3, cc = (f4i & 7) * 4;
            Vs[buf][r][cc+0] = to_tf32(varg[it].x);
            Vs[buf][r][cc+1] = to_tf32(varg[it].y);
            Vs[buf][r][cc+2] = to_tf32(varg[it].z);
            Vs[buf][r][cc+3] = to_tf32(varg[it].w);
        }
    };

    fetch(0);
    stash(0);
    __syncthreads();
    int cur = 0;
    for (int kt = 0; kt < 16; kt++) {
        if (kt + 1 < 16) fetch((kt + 1) * 32);
        #pragma unroll
        for (int ks = 0; ks < 32; ks += 8) {
            uint32_t af[4], bf[4][2];
            int mb = wid * 16;
            af[0] = __float_as_uint(Ps[cur][ks + tig    ][mb + gid    ]);
            af[1] = __float_as_uint(Ps[cur][ks + tig    ][mb + gid + 8]);
            af[2] = __float_as_uint(Ps[cur][ks + tig + 4][mb + gid    ]);
            af[3] = __float_as_uint(Ps[cur][ks + tig + 4][mb + gid + 8]);
            #pragma unroll
            for (int ni = 0; ni < 4; ni++) {
                int nb = ni * 8;
                bf[ni][0] = __float_as_uint(Vs[cur][ks + tig    ][nb + gid]);
                bf[ni][1] = __float_as_uint(Vs[cur][ks + tig + 4][nb + gid]);
            }
            #pragma unroll
            for (int ni = 0; ni < 4; ni++)
                MMA_TF32(c[ni][0], c[ni][1], c[ni][2], c[ni][3],
                         af[0], af[1], af[2], af[3], bf[ni][0], bf[ni][1]);
        }
        if (kt + 1 < 16) {
            stash(cur ^ 1);
            __syncthreads();
            cur ^= 1;
        }
    }

    #pragma unroll
    for (int ni = 0; ni < 4; ni++)
        #pragma unroll
        for (int hh = 0; hh < 2; hh++) {
            int gq = q0 + wid * 16 + gid + hh * 8;
            int gd = ni * 8 + tig * 2;
            g_att[(b*LL + gq)*DM + h*DK + gd + 0] = c[ni][hh*2 + 0];
            g_att[(b*LL + gq)*DM + h*DK + gd + 1] = c[ni][hh*2 + 1];
        }
}

// ---------------- host orchestration ----------------
extern "C" void kernel_launch(void* const* d_in, const int* in_sizes, int n_in,
                              void* d_out, int out_size)
{
    const float* x          = (const float*)d_in[0];
    const float* memory     = (const float*)d_in[1];
    // d_in[2] src_mask (all true), d_in[3] tgt_mask (unused)
    const float* in_proj_w  = (const float*)d_in[4];
    const float* conv_w     = (const float*)d_in[5];
    const float* conv_b     = (const float*)d_in[6];
    const float* x_proj_w   = (const float*)d_in[7];
    const float* dt_proj_w  = (const float*)d_in[8];
    const float* dt_proj_b  = (const float*)d_in[9];
    const float* A_log      = (const float*)d_in[10];
    const float* Dp         = (const float*)d_in[11];
    const float* out_proj_w = (const float*)d_in[12];
    const float* norm1_a    = (const float*)d_in[13];
    const float* norm1_b    = (const float*)d_in[14];
    const float* norm2_a    = (const float*)d_in[15];
    const float* norm2_b    = (const float*)d_in[16];
    const float* norm3_a    = (const float*)d_in[17];
    const float* norm3_b    = (const float*)d_in[18];
    const float* wq_w       = (const float*)d_in[19];
    const float* wq_b       = (const float*)d_in[20];
    const float* wk_w       = (const float*)d_in[21];
    const float* wk_b       = (const float*)d_in[22];
    const float* wv_w       = (const float*)d_in[23];
    const float* wv_b       = (const float*)d_in[24];
    const float* wo_w       = (const float*)d_in[25];
    const float* wo_b       = (const float*)d_in[26];
    const float* w1_w       = (const float*)d_in[27];
    const float* w1_b       = (const float*)d_in[28];
    const float* w2_w       = (const float*)d_in[29];
    const float* w2_b       = (const float*)d_in[30];
    float* out = (float*)d_out;

    float *p_ln, *p_xz, *p_u, *p_dbl, *p_dt, *p_yact, *p_h, *p_h2;
    float *p_q, *p_k, *p_v, *p_att, *p_ffh, *p_part;
    cudaGetSymbolAddress((void**)&p_ln,   g_ln);
    cudaGetSymbolAddress((void**)&p_xz,   g_xz);
    cudaGetSymbolAddress((void**)&p_u,    g_u);
    cudaGetSymbolAddress((void**)&p_dbl,  g_dbl);
    cudaGetSymbolAddress((void**)&p_dt,   g_dt);
    cudaGetSymbolAddress((void**)&p_yact, g_yact);
    cudaGetSymbolAddress((void**)&p_h,    g_h);
    cudaGetSymbolAddress((void**)&p_h2,   g_h2);
    cudaGetSymbolAddress((void**)&p_q,    g_q);
    cudaGetSymbolAddress((void**)&p_k,    g_k);
    cudaGetSymbolAddress((void**)&p_v,    g_v);
    cudaGetSymbolAddress((void**)&p_att,  g_att);
    cudaGetSymbolAddress((void**)&p_ffh,  g_ffh);
    cudaGetSymbolAddress((void**)&p_part, g_part);

    // ---- Mamba block ----
    ln_kernel<<<ROWS, DM>>>(x, norm1_a, norm1_b, p_ln);
    // xz = ln1 @ in_proj_w^T  (1024x2048x256): 64x64 -> 512 blocks
    launch_tgemm<64,64,32,2,2, 0,false,false,false>(p_ln, DM, in_proj_w, nullptr, nullptr, p_xz, XZW, ROWS, XZW, DM);
    // u = silu(causal_conv(xi))
    conv_silu_kernel<<<(ROWS*DI+255)/256, 256>>>(conv_w, conv_b);
    // dbl = u @ x_proj_w^T  (1024x272x1024): split-K4, 64x64 -> 320 blocks
    launch_tgemm<64,64,32,2,2, 0,false,false,true, 4,true>(p_u, DI, x_proj_w, nullptr, nullptr, p_part, XP_PAD, ROWS, DBLW, DI);
    reduce4_x<<<(ROWS*(DBLW/4)+255)/256, 256>>>();
    // dt = softplus(dbl[:, :16] @ dt_proj_w^T + b)  (1024x1024x16): 256 blocks
    launch_tgemm<64,64,16,2,2, 2,true,false,false>(p_dbl, DBLW, dt_proj_w, dt_proj_b, nullptr, p_dt, DI, ROWS, DI, DTR);
    // selective scan + (y + u*Dp)*silu(z)
    scan_kernel<<<(BB*DI)/8, 256>>>(A_log, Dp);
    // h = x + yact @ out_proj_w^T  (1024x256x1024): 64x32 -> 128 blocks
    launch_tgemm<64,32,32,4,1, 0,false,true,false>(p_yact, DI, out_proj_w, nullptr, x, p_h, DM, ROWS, DM, DI);

    // ---- Cross attention ----
    ln_kernel<<<ROWS, DM>>>(p_h, norm2_a, norm2_b, p_ln);
    launch_tgemm<64,32,32,4,1, 0,true,false,false>(p_ln,   DM, wq_w, wq_b, nullptr, p_q, DM, ROWS, DM, DM);
    launch_tgemm<64,32,32,4,1, 0,true,false,false>(memory, DM, wk_w, wk_b, nullptr, p_k, DM, BB*LM, DM, DM);
    launch_tgemm<64,32,32,4,1, 0,true,false,false>(memory, DM, wv_w, wv_b, nullptr, p_v, DM, BB*LM, DM, DM);
    {
        dim3 sgrid(LM/64, LL/64, NBH);
        score_mma<<<sgrid, 128>>>();
        softmax_kernel<<<NBH*LL, 128>>>();
        dim3 pgrid(LL/64, NBH);
        pv_mma<<<pgrid, 128>>>();
    }
    // h2 = h + att @ wo_w^T + wo_b
    launch_tgemm<64,32,32,4,1, 0,true,true,false>(p_att, DM, wo_w, wo_b, p_h, p_h2, DM, ROWS, DM, DM);

    // ---- FFN ----
    ln_kernel<<<ROWS, DM>>>(p_h2, norm3_a, norm3_b, p_ln);
    // FF1 (1024x1024x256): 64x64 -> 256 blocks
    launch_tgemm<64,64,32,2,2, 1,true,false,false>(p_ln, DM, w1_w, w1_b, nullptr, p_ffh, DFF, ROWS, DFF, DM);
    // FF2 (1024x256x1024): 64x32 -> 128 blocks
    launch_tgemm<64,32,32,4,1, 0,true,true,false>(p_ffh, DFF, w2_w, w2_b, p_h2, out, DM, ROWS, DM, DFF);
}